// round 7
// baseline (speedup 1.0000x reference)
#include <cuda_runtime.h>
#include <cuda_bf16.h>
#include <mma.h>
#include <cstdint>

using namespace nvcuda;

#define HH 192
#define WW 192
#define HWSZ (192*192)
#define CC 64
#define KTAPS 49
#define PADK 3

#define FMA2(d,a,b,c) asm("fma.rn.f32x2 %0, %1, %2, %3;" : "=l"(d) : "l"(a), "l"(b), "l"(c))
#define MUL2(d,a,b)   asm("mul.rn.f32x2 %0, %1, %2;" : "=l"(d) : "l"(a), "l"(b))

typedef unsigned long long ull;

__device__ __forceinline__ ull packpair(float v) {
    unsigned int u = __float_as_uint(v);
    return ((ull)u << 32) | u;
}
__device__ __forceinline__ ull pack2(float lo, float hi) {
    return ((ull)__float_as_uint(hi) << 32) | __float_as_uint(lo);
}

// ---------------- scratch (no allocs allowed) ----------------
__device__ float g_rev [CC*HWSZ];
__device__ float g_fft [CC*HWSZ];
__device__ float g_e3  [CC*HWSZ];
__device__ float g_x1  [CC*HWSZ];
__device__ float g_encT[HWSZ*CC];        // NHWC
__device__ float g_e2pm[CC*64*576];      // [c][q=64][patch=576]
__device__ __nv_bfloat16 g_wbh[KTAPS*64*64];  // [k][o][c] hi
__device__ __nv_bfloat16 g_wbl[KTAPS*64*64];  // [k][o][c] lo
__device__ ull   g_wc2t2[9*64*64];       // [k][c][o] pairs
__device__ ull   g_wph [2*128*64];       // [half][j128][o64] pairs
__device__ ull   g_wpit2[64*64];         // [j][c] pairs
__device__ float g_gg  [64*64];          // [c][a*8+d]

// ---------------- precompute: FFT filter -> circular conv kernel ----------------
__global__ void k_prep_g(const float* __restrict__ fw) {
    int c = blockIdx.x;
    int t = threadIdx.x;
    int a = t >> 3, d = t & 7;
    const float ct[8] = {1.f, 0.70710678118654752f, 0.f, -0.70710678118654752f,
                        -1.f, -0.70710678118654752f, 0.f, 0.70710678118654752f};
    const float st[8] = {0.f, 0.70710678118654752f, 1.f, 0.70710678118654752f,
                         0.f, -0.70710678118654752f, -1.f, -0.70710678118654752f};
    const float* w = fw + c * 40;
    float re = 0.f;
    for (int u = 0; u < 8; u++) {
        float rp = w[u*5+0] + ((d & 1) ? -w[u*5+4] : w[u*5+4]);
        float ip = 0.f;
        #pragma unroll
        for (int v = 1; v <= 3; v++) {
            int vd = (v * d) & 7;
            rp += 2.f * w[u*5+v] * ct[vd];
            ip += 2.f * w[u*5+v] * st[vd];
        }
        int ua = (u * a) & 7;
        re += ct[ua] * rp - st[ua] * ip;
    }
    g_gg[c*64 + t] = re * (1.f/64.f);
}

// ---------------- precompute: fused deform weight -> bf16 hi/lo [k][o][c] ----------------
__global__ void k_prep_wbf(const float* __restrict__ wc1, const float* __restrict__ wd) {
    int idx = blockIdx.x * blockDim.x + threadIdx.x;   // k*4096 + c*64 + o
    if (idx >= KTAPS*64*64) return;
    int o = idx & 63, c = (idx >> 6) & 63, k = idx >> 12;
    float s = 0.f;
    for (int m = 0; m < 64; m++)
        s += wc1[o*64 + m] * wd[(m*64 + c)*49 + k];
    __nv_bfloat16 hi = __float2bfloat16(s);
    float hv = __bfloat162float(hi);
    __nv_bfloat16 lo = __float2bfloat16(s - hv);
    g_wbh[k*4096 + o*64 + c] = hi;
    g_wbl[k*4096 + o*64 + c] = lo;
}

// ---------------- precompute: weight transposes (pairs) ----------------
__global__ void k_prep_tr(const float* __restrict__ wc2, const float* __restrict__ wpo,
                          const float* __restrict__ wpi) {
    int idx = blockIdx.x * blockDim.x + threadIdx.x;
    if (idx < 9*4096) {
        int o = idx & 63, c = (idx >> 6) & 63, k = idx >> 12;
        g_wc2t2[idx] = packpair(wc2[(o*64 + c)*9 + k]);
    }
    if (idx < 2*128*64) {
        int half = idx >> 13, j = (idx >> 6) & 127, o = idx & 63;
        g_wph[idx] = packpair(wpo[(half*64 + o)*128 + j]);
    }
    if (idx < 4096) {
        int j = idx >> 6, c = idx & 63;
        g_wpit2[idx] = packpair(wpi[c*64 + j]);
    }
}

// ---------------- NCHW -> NHWC transpose of enc ----------------
__global__ void __launch_bounds__(256) k_transpose(const float* __restrict__ enc) {
    __shared__ float S[64][65];
    int tid = threadIdx.x;
    int p0 = blockIdx.x * 64;
    #pragma unroll
    for (int i = 0; i < 16; i++) {
        int e = i*256 + tid;
        S[e >> 6][e & 63] = enc[(e >> 6)*HWSZ + p0 + (e & 63)];
    }
    __syncthreads();
    #pragma unroll
    for (int i = 0; i < 16; i++) {
        int e = i*256 + tid;
        g_encT[p0*64 + e] = S[e & 63][e >> 6];
    }
}

// ---------------- deform conv via WMMA bf16-split, 16x8 tile, 2 blocks/SM ----------------
// smem (bytes):
//   VHI [128 px][72 bf16] stride 144B : 0..18432
//   VLO 18432..36864
//   WHI [64 o][72 bf16]   stride 144B : 36864..46080
//   WLO 46080..55296
//   SIDX 55296..57344   (int[4][128])
//   SWT  57344..59392   (float[4][128])
// readout reuses VHI/VLO as float D[128][68] (34816 B)
#define DW_VHI  0
#define DW_VLO  18432
#define DW_WHI  36864
#define DW_WLO  46080
#define DW_SIDX 55296
#define DW_SWT  57344
#define DW_SMEM 59392

__global__ void __launch_bounds__(256, 2) k_deform_wmma(const float* __restrict__ off,
                                                        const float* __restrict__ msk) {
    extern __shared__ char dsm[];
    __nv_bfloat16* Vhi = (__nv_bfloat16*)(dsm + DW_VHI);
    __nv_bfloat16* Vlo = (__nv_bfloat16*)(dsm + DW_VLO);
    __nv_bfloat16* Whi = (__nv_bfloat16*)(dsm + DW_WHI);
    __nv_bfloat16* Wlo = (__nv_bfloat16*)(dsm + DW_WLO);
    int*   sIdx = (int*)(dsm + DW_SIDX);
    float* sWt  = (float*)(dsm + DW_SWT);
    const float* encT = g_encT;

    int tid = threadIdx.x;
    int wid = tid >> 5;
    int ph = blockIdx.y * 8, pw = blockIdx.x * 16;    // 16w x 8h tile, 128 px
    int ly = (tid & 127) >> 4, lx = tid & 15;
    int h = ph + ly, w = pw + lx;
    int sp = h * WW + w;

    wmma::fragment<wmma::accumulator, 16, 16, 16, float> dfr[4];
    #pragma unroll
    for (int n = 0; n < 4; n++) wmma::fill_fragment(dfr[n], 0.f);

    for (int k = 0; k < KTAPS; k++) {
        // ---- stage W hi/lo: [o][c] global -> [o][72] smem ----
        #pragma unroll
        for (int i = 0; i < 2; i++) {
            int f = i*256 + tid;          // 0..511 : row = f>>3, chunk = f&7
            int row = f >> 3, ch = f & 7;
            *(float4*)((char*)Whi + row*144 + ch*16) =
                *(const float4*)(g_wbh + k*4096 + row*64 + ch*8);
            *(float4*)((char*)Wlo + row*144 + ch*16) =
                *(const float4*)(g_wbl + k*4096 + row*64 + ch*8);
        }
        // ---- sampling params (threads 0..127, one per pixel) ----
        if (tid < 128) {
            float dy = off[(2*k)*HWSZ + sp];
            float dx = off[(2*k+1)*HWSZ + sp];
            float m  = msk[k*HWSZ + sp];
            float yy = (float)(h - PADK + k/7) + dy;
            float xx = (float)(w - PADK + k%7) + dx;
            float y0f = floorf(yy), x0f = floorf(xx);
            float wy = yy - y0f, wx = xx - x0f;
            int y0 = (int)y0f, x0 = (int)x0f;
            int y1 = y0 + 1,   x1 = x0 + 1;
            bool vy0 = (y0 >= 0) && (y0 < HH), vy1 = (y1 >= 0) && (y1 < HH);
            bool vx0 = (x0 >= 0) && (x0 < WW), vx1 = (x1 >= 0) && (x1 < WW);
            int y0c = min(max(y0, 0), HH-1), y1c = min(max(y1, 0), HH-1);
            int x0c = min(max(x0, 0), WW-1), x1c = min(max(x1, 0), WW-1);
            sIdx[0*128 + tid] = (y0c*WW + x0c) * 64;
            sIdx[1*128 + tid] = (y0c*WW + x1c) * 64;
            sIdx[2*128 + tid] = (y1c*WW + x0c) * 64;
            sIdx[3*128 + tid] = (y1c*WW + x1c) * 64;
            sWt[0*128 + tid] = (vy0 && vx0) ? (1.f-wy)*(1.f-wx)*m : 0.f;
            sWt[1*128 + tid] = (vy0 && vx1) ? (1.f-wy)*wx*m       : 0.f;
            sWt[2*128 + tid] = (vy1 && vx0) ? wy*(1.f-wx)*m       : 0.f;
            sWt[3*128 + tid] = (vy1 && vx1) ? wy*wx*m             : 0.f;
        }
        __syncthreads();

        // ---- gather: bilinear fp32, split bf16 hi/lo into V[p][72] ----
        int c4 = tid & 15;
        #pragma unroll
        for (int it = 0; it < 2; it++) {
            int pq = (tid >> 4) + it * 16;   // 0..31 pixel-quads
            int p0 = pq * 4;
            #pragma unroll
            for (int pp = 0; pp < 4; pp++) {
                int p = p0 + pp;
                const float4 t0 = *(const float4*)(encT + sIdx[0*128 + p] + (c4 << 2));
                const float4 t1 = *(const float4*)(encT + sIdx[1*128 + p] + (c4 << 2));
                const float4 t2 = *(const float4*)(encT + sIdx[2*128 + p] + (c4 << 2));
                const float4 t3 = *(const float4*)(encT + sIdx[3*128 + p] + (c4 << 2));
                float w0 = sWt[0*128 + p], w1 = sWt[1*128 + p];
                float w2 = sWt[2*128 + p], w3 = sWt[3*128 + p];
                float v0 = w0*t0.x + w1*t1.x + w2*t2.x + w3*t3.x;
                float v1 = w0*t0.y + w1*t1.y + w2*t2.y + w3*t3.y;
                float v2 = w0*t0.z + w1*t1.z + w2*t2.z + w3*t3.z;
                float v3 = w0*t0.w + w1*t1.w + w2*t2.w + w3*t3.w;
                uint32_t h01, h23, l01, l23;
                asm("cvt.rn.bf16x2.f32 %0, %1, %2;" : "=r"(h01) : "f"(v1), "f"(v0));
                asm("cvt.rn.bf16x2.f32 %0, %1, %2;" : "=r"(h23) : "f"(v3), "f"(v2));
                float hv0 = __uint_as_float(h01 << 16);
                float hv1 = __uint_as_float(h01 & 0xffff0000u);
                float hv2 = __uint_as_float(h23 << 16);
                float hv3 = __uint_as_float(h23 & 0xffff0000u);
                asm("cvt.rn.bf16x2.f32 %0, %1, %2;" : "=r"(l01) : "f"(v1 - hv1), "f"(v0 - hv0));
                asm("cvt.rn.bf16x2.f32 %0, %1, %2;" : "=r"(l23) : "f"(v3 - hv3), "f"(v2 - hv2));
                *(uint2*)((char*)Vhi + p*144 + c4*8) = make_uint2(h01, h23);
                *(uint2*)((char*)Vlo + p*144 + c4*8) = make_uint2(l01, l23);
            }
        }
        __syncthreads();

        // ---- WMMA: warp wid owns pixel rows wid*16..+15 ----
        #pragma unroll
        for (int kc = 0; kc < 4; kc++) {
            wmma::fragment<wmma::matrix_a, 16, 16, 16, __nv_bfloat16, wmma::row_major> ah, al;
            wmma::load_matrix_sync(ah, Vhi + (wid*16)*72 + kc*16, 72);
            wmma::load_matrix_sync(al, Vlo + (wid*16)*72 + kc*16, 72);
            #pragma unroll
            for (int n = 0; n < 4; n++) {
                wmma::fragment<wmma::matrix_b, 16, 16, 16, __nv_bfloat16, wmma::col_major> bh, bl;
                wmma::load_matrix_sync(bh, Whi + (n*16)*72 + kc*16, 72);
                wmma::load_matrix_sync(bl, Wlo + (n*16)*72 + kc*16, 72);
                wmma::mma_sync(dfr[n], ah, bh, dfr[n]);
                wmma::mma_sync(dfr[n], al, bh, dfr[n]);
                wmma::mma_sync(dfr[n], ah, bl, dfr[n]);
            }
        }
        __syncthreads();
    }

    // ---- readout: frags -> smem D[128][68] -> g_rev NCHW ----
    float* Dsh = (float*)dsm;
    #pragma unroll
    for (int n = 0; n < 4; n++)
        wmma::store_matrix_sync(Dsh + (wid*16)*68 + n*16, dfr[n], 68, wmma::mem_row_major);
    __syncthreads();
    {
        int p = tid & 127;
        int hf = tid >> 7;                 // channel half
        int base = (ph + (p >> 4))*WW + pw + (p & 15);
        #pragma unroll
        for (int i = 0; i < 32; i++) {
            int o = hf*32 + i;
            g_rev[o*HWSZ + base] = Dsh[p*68 + o];
        }
    }
}

// ---------------- 1x1 conv on enc -> patch-major e2pm[c][q][patch] ----------------
__global__ void __launch_bounds__(256) k_conv1x1pm(const float* __restrict__ enc) {
    __shared__ ull Wt[64*64];
    int tid = threadIdx.x;
    {
        const ulonglong2* src = (const ulonglong2*)g_wpit2;
        ulonglong2* dst = (ulonglong2*)Wt;
        #pragma unroll
        for (int i = 0; i < 8; i++) dst[tid + i*256] = src[tid + i*256];
    }
    __syncthreads();

    int base = blockIdx.x * 512;
    int p = base + (tid & 7) + (tid >> 3) * 16;
    int p2 = p + 8;

    ull acc[64];
    #pragma unroll
    for (int c = 0; c < 64; c++) acc[c] = 0ull;

    for (int j = 0; j < 64; j++) {
        ull v = pack2(enc[j*HWSZ + p], enc[j*HWSZ + p2]);
        const ulonglong2* wrow = (const ulonglong2*)(Wt + j*64);
        #pragma unroll
        for (int cc = 0; cc < 32; cc++) {
            ulonglong2 wv = wrow[cc];
            FMA2(acc[2*cc],   wv.x, v, acc[2*cc]);
            FMA2(acc[2*cc+1], wv.y, v, acc[2*cc+1]);
        }
    }

    int h = p / 192, w = p % 192;
    int q = (h & 7)*8 + (w & 7);
    int pat = (h >> 3)*24 + (w >> 3);
    #pragma unroll
    for (int c = 0; c < 64; c++)
        *(ull*)&g_e2pm[c*(64*576) + q*576 + pat] = acc[c];
}

// ---------------- per-patch circular conv as dense GEMM per channel ----------------
#define FFT_SMEM (50176 + 32768)

__global__ void __launch_bounds__(256, 1) k_fftgemm() {
    extern __shared__ char dsm[];
    float* Es = (float*)dsm;
    ull*   Wp = (ull*)(dsm + 50176);

    int tid = threadIdx.x;
    int lane = tid & 31;
    int c = blockIdx.x, pg = blockIdx.y;

    #pragma unroll
    for (int i = 0; i < 12; i++) {
        int f = i*256 + tid;
        int q = f / 48, r = f % 48;
        *(float4*)&Es[q*196 + r*4] =
            *(const float4*)&g_e2pm[c*(64*576) + q*576 + pg*192 + r*4];
    }
    #pragma unroll
    for (int i = 0; i < 16; i++) {
        int f = i*256 + tid;
        int q = f >> 6, p = f & 63;
        int idx = (((p >> 3) - (q >> 3)) & 7)*8 + (((p & 7) - (q & 7)) & 7);
        Wp[f] = packpair(g_gg[c*64 + idx]);
    }
    __syncthreads();

    int pbase = (tid >> 5) * 8;
    ull acc[8][3];
    #pragma unroll
    for (int o = 0; o < 8; o++)
        #pragma unroll
        for (int g = 0; g < 3; g++) acc[o][g] = 0ull;

    #pragma unroll 8
    for (int q = 0; q < 64; q++) {
        ull A0 = *(const ull*)&Es[q*196 + 0*64 + 2*lane];
        ull A1 = *(const ull*)&Es[q*196 + 1*64 + 2*lane];
        ull A2 = *(const ull*)&Es[q*196 + 2*64 + 2*lane];
        const ulonglong2* wp = (const ulonglong2*)(Wp + q*64 + pbase);
        ulonglong2 w01 = wp[0], w23 = wp[1], w45 = wp[2], w67 = wp[3];
        ull wv[8] = {w01.x, w01.y, w23.x, w23.y, w45.x, w45.y, w67.x, w67.y};
        #pragma unroll
        for (int o = 0; o < 8; o++) {
            FMA2(acc[o][0], wv[o], A0, acc[o][0]);
            FMA2(acc[o][1], wv[o], A1, acc[o][1]);
            FMA2(acc[o][2], wv[o], A2, acc[o][2]);
        }
    }

    float* dst = g_fft + c*HWSZ;
    #pragma unroll
    for (int o = 0; o < 8; o++) {
        int p = pbase + o;
        int py = p >> 3, px = p & 7;
        #pragma unroll
        for (int g = 0; g < 3; g++) {
            int pat = pg*192 + g*64 + 2*lane;
            float lo = __uint_as_float((unsigned int)(acc[o][g] & 0xffffffffull));
            float hi = __uint_as_float((unsigned int)(acc[o][g] >> 32));
            dst[((pat/24)*8 + py)*WW + (pat%24)*8 + px] = lo;
            pat++;
            dst[((pat/24)*8 + py)*WW + (pat%24)*8 + px] = hi;
        }
    }
}

// ---------------- 3x3 conv (pad 1), input = g_fft + g_rev, 16x8 tile ----------------
// smem: Vsh float[64][132] 33792 | Wp ull[64*64] 32768
#define C3_SMEM (33792 + 32768)

__global__ void __launch_bounds__(256, 2) k_conv3() {
    extern __shared__ char dsm[];
    float* Vsh = (float*)dsm;
    ull*   Wp  = (ull*)(dsm + 33792);

    int tid = threadIdx.x;
    int lane = tid & 31;
    int ot = (tid >> 5) * 8;
    int ph = blockIdx.y * 8, pw = blockIdx.x * 16;

    ull acc[8][2];
    #pragma unroll
    for (int o = 0; o < 8; o++)
        #pragma unroll
        for (int pr = 0; pr < 2; pr++) acc[o][pr] = 0ull;

    for (int k = 0; k < 9; k++) {
        int dy = k/3 - 1, dx = k%3 - 1;
        {
            const ulonglong2* wsrc = (const ulonglong2*)(g_wc2t2 + k*4096);
            ulonglong2* wdst = (ulonglong2*)Wp;
            #pragma unroll
            for (int i = 0; i < 8; i++) wdst[tid + i*256] = wsrc[tid + i*256];
        }
        // stage V: 64c x 128px, 32 elements per thread
        #pragma unroll
        for (int i = 0; i < 32; i++) {
            int e = i*256 + tid;
            int c = e >> 7, p = e & 127;
            int h = ph + (p >> 4) + dy, w = pw + (p & 15) + dx;
            bool ok = (h >= 0) && (h < HH) && (w >= 0) && (w < WW);
            int sp = h*WW + w;
            Vsh[c*132 + p] = ok ? (g_fft[c*HWSZ + sp] + g_rev[c*HWSZ + sp]) : 0.f;
        }
        __syncthreads();

        #pragma unroll 8
        for (int c = 0; c < 64; c++) {
            union { float4 f; ull u[2]; } A;
            A.f = *(const float4*)&Vsh[c*132 + 4*lane];
            const ulonglong2* wp = (const ulonglong2*)(Wp + c*64 + ot);
            ulonglong2 w01 = wp[0], w23 = wp[1], w45 = wp[2], w67 = wp[3];
            ull wv[8] = {w01.x, w01.y, w23.x, w23.y, w45.x, w45.y, w67.x, w67.y};
            #pragma unroll
            for (int o = 0; o < 8; o++) {
                FMA2(acc[o][0], wv[o], A.u[0], acc[o][0]);
                FMA2(acc[o][1], wv[o], A.u[1], acc[o][1]);
            }
        }
        __syncthreads();
    }

    #pragma unroll
    for (int o = 0; o < 8; o++) {
        float* orow = g_e3 + (ot + o)*HWSZ;
        #pragma unroll
        for (int pr = 0; pr < 2; pr++) {
            int p0 = 4*lane + pr*2;
            int py = p0 >> 4, px = p0 & 15;
            *(ull*)(orow + (ph + py)*WW + pw + px) = acc[o][pr];
        }
    }
}

// ---------------- proj(128->64 per half) + gate ----------------
#define PJ_SMEM (66560 + 66560 + 65536)

__global__ void __launch_bounds__(256, 1) k_projhalf(const float* __restrict__ dec,
                                                     float* __restrict__ out, int half) {
    extern __shared__ char dsm[];
    float* Va = (float*)dsm;
    float* Vb = (float*)(dsm + 66560);
    ull*   Wp = (ull*)(dsm + 2*66560);

    int tid = threadIdx.x;
    int lane = tid & 31;
    int ot = (tid >> 5) * 8;
    int ph = blockIdx.y * 16, pw = blockIdx.x * 16;
    int sy = tid >> 4, sx = tid & 15;
    int sp = (ph + sy)*WW + pw + sx;

    {
        const ulonglong2* wsrc = (const ulonglong2*)(g_wph + half*8192);
        ulonglong2* wdst = (ulonglong2*)Wp;
        #pragma unroll
        for (int i = 0; i < 16; i++) wdst[tid + i*256] = wsrc[tid + i*256];
    }
    #pragma unroll
    for (int c = 0; c < 64; c++) {
        Va[c*260 + tid] = g_e3[c*HWSZ + sp];
        Vb[c*260 + tid] = dec[c*HWSZ + sp];
    }
    __syncthreads();

    ull acc[8][4];
    #pragma unroll
    for (int o = 0; o < 8; o++)
        #pragma unroll
        for (int pr = 0; pr < 4; pr++) acc[o][pr] = 0ull;

    #pragma unroll 4
    for (int c = 0; c < 64; c++) {
        union { float4 f; ull u[2]; } A, B;
        A.f = *(const float4*)&Va[c*260 + 4*lane];
        B.f = *(const float4*)&Va[c*260 + 128 + 4*lane];
        const ulonglong2* wp = (const ulonglong2*)(Wp + c*64 + ot);
        ulonglong2 w01 = wp[0], w23 = wp[1], w45 = wp[2], w67 = wp[3];
        ull wv[8] = {w01.x, w01.y, w23.x, w23.y, w45.x, w45.y, w67.x, w67.y};
        #pragma unroll
        for (int o = 0; o < 8; o++) {
            FMA2(acc[o][0], wv[o], A.u[0], acc[o][0]);
            FMA2(acc[o][1], wv[o], A.u[1], acc[o][1]);
            FMA2(acc[o][2], wv[o], B.u[0], acc[o][2]);
            FMA2(acc[o][3], wv[o], B.u[1], acc[o][3]);
        }
    }
    #pragma unroll 4
    for (int c = 0; c < 64; c++) {
        union { float4 f; ull u[2]; } A, B;
        A.f = *(const float4*)&Vb[c*260 + 4*lane];
        B.f = *(const float4*)&Vb[c*260 + 128 + 4*lane];
        const ulonglong2* wp = (const ulonglong2*)(Wp + (64 + c)*64 + ot);
        ulonglong2 w01 = wp[0], w23 = wp[1], w45 = wp[2], w67 = wp[3];
        ull wv[8] = {w01.x, w01.y, w23.x, w23.y, w45.x, w45.y, w67.x, w67.y};
        #pragma unroll
        for (int o = 0; o < 8; o++) {
            FMA2(acc[o][0], wv[o], A.u[0], acc[o][0]);
            FMA2(acc[o][1], wv[o], A.u[1], acc[o][1]);
            FMA2(acc[o][2], wv[o], B.u[0], acc[o][2]);
            FMA2(acc[o][3], wv[o], B.u[1], acc[o][3]);
        }
    }

    if (half == 0) {
        #pragma unroll
        for (int o = 0; o < 8; o++) {
            float* orow = g_x1 + (ot + o)*HWSZ;
            #pragma unroll
            for (int pr = 0; pr < 4; pr++) {
                int p0 = ((pr >> 1) ? 128 : 0) + 4*lane + (pr & 1)*2;
                int py = p0 >> 4, px = p0 & 15;
                *(ull*)(orow + (ph + py)*WW + pw + px) = acc[o][pr];
            }
        }
    } else {
        #pragma unroll
        for (int o = 0; o < 8; o++) {
            const float* xrow = g_x1 + (ot + o)*HWSZ;
            float* orow = out + (ot + o)*HWSZ;
            #pragma unroll
            for (int pr = 0; pr < 4; pr++) {
                int p0 = ((pr >> 1) ? 128 : 0) + 4*lane + (pr & 1)*2;
                int py = p0 >> 4, px = p0 & 15;
                int gi = (ph + py)*WW + pw + px;
                ull x1v = *(const ull*)(xrow + gi);
                ull r;
                MUL2(r, x1v, acc[o][pr]);
                *(ull*)(orow + gi) = r;
            }
        }
    }
}

extern "C" void kernel_launch(void* const* d_in, const int* in_sizes, int n_in,
                              void* d_out, int out_size) {
    const float* enc  = (const float*)d_in[0];
    const float* dec  = (const float*)d_in[1];
    const float* ioff = (const float*)d_in[2];
    const float* iw   = (const float*)d_in[3];
    const float* wpi  = (const float*)d_in[4];
    const float* fftw = (const float*)d_in[5];
    const float* wpo  = (const float*)d_in[6];
    const float* wdef = (const float*)d_in[7];
    const float* wc1  = (const float*)d_in[8];
    const float* wc2  = (const float*)d_in[9];
    float* out = (float*)d_out;

    cudaFuncSetAttribute(k_deform_wmma, cudaFuncAttributeMaxDynamicSharedMemorySize, DW_SMEM);
    cudaFuncSetAttribute(k_fftgemm,     cudaFuncAttributeMaxDynamicSharedMemorySize, FFT_SMEM);
    cudaFuncSetAttribute(k_conv3,       cudaFuncAttributeMaxDynamicSharedMemorySize, C3_SMEM);
    cudaFuncSetAttribute(k_projhalf,    cudaFuncAttributeMaxDynamicSharedMemorySize, PJ_SMEM);

    dim3 gdef(12, 24);    // 16w x 8h tiles
    dim3 g12(12, 12);
    dim3 gfft(64, 3);

    k_transpose  <<<576, 256>>>(enc);
    k_prep_wbf   <<<(KTAPS*4096 + 255)/256, 256>>>(wc1, wdef);
    k_prep_g     <<<64, 64>>>(fftw);
    k_deform_wmma<<<gdef, 256, DW_SMEM>>>(ioff, iw);
    k_prep_tr    <<<144, 256>>>(wc2, wpo, wpi);
    k_conv1x1pm  <<<72, 256>>>(enc);
    k_fftgemm    <<<gfft, 256, FFT_SMEM>>>();
    k_conv3      <<<gdef, 256, C3_SMEM>>>();
    k_projhalf   <<<g12, 256, PJ_SMEM>>>(dec, out, 0);
    k_projhalf   <<<g12, 256, PJ_SMEM>>>(dec, out, 1);
}

// round 8
// speedup vs baseline: 1.0805x; 1.0805x over previous
#include <cuda_runtime.h>
#include <cuda_bf16.h>
#include <mma.h>
#include <cstdint>

using namespace nvcuda;

#define HH 192
#define WW 192
#define HWSZ (192*192)
#define CC 64
#define KTAPS 49
#define PADK 3

#define FMA2(d,a,b,c) asm("fma.rn.f32x2 %0, %1, %2, %3;" : "=l"(d) : "l"(a), "l"(b), "l"(c))
#define MUL2(d,a,b)   asm("mul.rn.f32x2 %0, %1, %2;" : "=l"(d) : "l"(a), "l"(b))

typedef unsigned long long ull;

__device__ __forceinline__ ull packpair(float v) {
    unsigned int u = __float_as_uint(v);
    return ((ull)u << 32) | u;
}
__device__ __forceinline__ ull pack2(float lo, float hi) {
    return ((ull)__float_as_uint(hi) << 32) | __float_as_uint(lo);
}

// ---------------- scratch (no allocs allowed) ----------------
__device__ float g_rev [CC*HWSZ];
__device__ float g_fft [CC*HWSZ];
__device__ float g_e3  [CC*HWSZ];
__device__ float g_encT[HWSZ*CC];        // NHWC
__device__ float g_e2pm[CC*64*576];      // [c][q=64][patch=576]
__device__ __nv_bfloat16 g_wbh[KTAPS*64*64];  // [k][o][c] hi
__device__ __nv_bfloat16 g_wbl[KTAPS*64*64];  // [k][o][c] lo
__device__ ull   g_wc2t2[9*64*64];       // [k][c][o] pairs
__device__ float g_wpT [128*128];        // [j128][o128] plain (proj weights)
__device__ ull   g_wpit2[64*64];         // [j][c] pairs
__device__ float g_gg  [64*64];          // [c][a*8+d]

// ---------------- precompute: FFT filter -> circular conv kernel ----------------
__global__ void k_prep_g(const float* __restrict__ fw) {
    int c = blockIdx.x;
    int t = threadIdx.x;
    int a = t >> 3, d = t & 7;
    const float ct[8] = {1.f, 0.70710678118654752f, 0.f, -0.70710678118654752f,
                        -1.f, -0.70710678118654752f, 0.f, 0.70710678118654752f};
    const float st[8] = {0.f, 0.70710678118654752f, 1.f, 0.70710678118654752f,
                         0.f, -0.70710678118654752f, -1.f, -0.70710678118654752f};
    const float* w = fw + c * 40;
    float re = 0.f;
    for (int u = 0; u < 8; u++) {
        float rp = w[u*5+0] + ((d & 1) ? -w[u*5+4] : w[u*5+4]);
        float ip = 0.f;
        #pragma unroll
        for (int v = 1; v <= 3; v++) {
            int vd = (v * d) & 7;
            rp += 2.f * w[u*5+v] * ct[vd];
            ip += 2.f * w[u*5+v] * st[vd];
        }
        int ua = (u * a) & 7;
        re += ct[ua] * rp - st[ua] * ip;
    }
    g_gg[c*64 + t] = re * (1.f/64.f);
}

// ---------------- precompute: fused deform weight -> bf16 hi/lo [k][o][c] ----------------
__global__ void k_prep_wbf(const float* __restrict__ wc1, const float* __restrict__ wd) {
    int idx = blockIdx.x * blockDim.x + threadIdx.x;   // k*4096 + c*64 + o
    if (idx >= KTAPS*64*64) return;
    int o = idx & 63, c = (idx >> 6) & 63, k = idx >> 12;
    float s = 0.f;
    for (int m = 0; m < 64; m++)
        s += wc1[o*64 + m] * wd[(m*64 + c)*49 + k];
    __nv_bfloat16 hi = __float2bfloat16(s);
    float hv = __bfloat162float(hi);
    __nv_bfloat16 lo = __float2bfloat16(s - hv);
    g_wbh[k*4096 + o*64 + c] = hi;
    g_wbl[k*4096 + o*64 + c] = lo;
}

// ---------------- precompute: weight transposes ----------------
__global__ void k_prep_tr(const float* __restrict__ wc2, const float* __restrict__ wpo,
                          const float* __restrict__ wpi) {
    int idx = blockIdx.x * blockDim.x + threadIdx.x;
    if (idx < 9*4096) {
        int o = idx & 63, c = (idx >> 6) & 63, k = idx >> 12;
        g_wc2t2[idx] = packpair(wc2[(o*64 + c)*9 + k]);
    }
    if (idx < 128*128) {                        // [j][o] <- wpo[o][j]
        int j = idx >> 7, o = idx & 127;
        g_wpT[idx] = wpo[o*128 + j];
    }
    if (idx < 4096) {
        int j = idx >> 6, c = idx & 63;
        g_wpit2[idx] = packpair(wpi[c*64 + j]);
    }
}

// ---------------- NCHW -> NHWC transpose of enc ----------------
__global__ void __launch_bounds__(256) k_transpose(const float* __restrict__ enc) {
    __shared__ float S[64][65];
    int tid = threadIdx.x;
    int p0 = blockIdx.x * 64;
    #pragma unroll
    for (int i = 0; i < 16; i++) {
        int e = i*256 + tid;
        S[e >> 6][e & 63] = enc[(e >> 6)*HWSZ + p0 + (e & 63)];
    }
    __syncthreads();
    #pragma unroll
    for (int i = 0; i < 16; i++) {
        int e = i*256 + tid;
        g_encT[p0*64 + e] = S[e & 63][e >> 6];
    }
}

// ---------------- deform conv via WMMA bf16-split, 16x8 tile, (4m,2n) warps ----------------
#define DW_VHI  0
#define DW_VLO  18432
#define DW_WHI  36864
#define DW_WLO  46080
#define DW_SIDX 55296
#define DW_SWT  57344
#define DW_SMEM 59392

__global__ void __launch_bounds__(256, 2) k_deform_wmma(const float* __restrict__ off,
                                                        const float* __restrict__ msk) {
    extern __shared__ char dsm[];
    __nv_bfloat16* Vhi = (__nv_bfloat16*)(dsm + DW_VHI);
    __nv_bfloat16* Vlo = (__nv_bfloat16*)(dsm + DW_VLO);
    __nv_bfloat16* Whi = (__nv_bfloat16*)(dsm + DW_WHI);
    __nv_bfloat16* Wlo = (__nv_bfloat16*)(dsm + DW_WLO);
    int*   sIdx = (int*)(dsm + DW_SIDX);
    float* sWt  = (float*)(dsm + DW_SWT);
    const float* encT = g_encT;

    int tid = threadIdx.x;
    int wid = tid >> 5;
    int mg = wid & 3, ng = wid >> 2;     // 4 m-groups x 2 n-groups
    int ph = blockIdx.y * 8, pw = blockIdx.x * 16;    // 16w x 8h tile, 128 px
    int ly = (tid & 127) >> 4, lx = tid & 15;
    int h = ph + ly, w = pw + lx;
    int sp = h * WW + w;

    wmma::fragment<wmma::accumulator, 16, 16, 16, float> dfr[2][2];
    #pragma unroll
    for (int mf = 0; mf < 2; mf++)
        #pragma unroll
        for (int nf = 0; nf < 2; nf++) wmma::fill_fragment(dfr[mf][nf], 0.f);

    for (int k = 0; k < KTAPS; k++) {
        // ---- stage W hi/lo: [o][c] global -> [o][72] smem ----
        #pragma unroll
        for (int i = 0; i < 2; i++) {
            int f = i*256 + tid;
            int row = f >> 3, ch = f & 7;
            *(float4*)((char*)Whi + row*144 + ch*16) =
                *(const float4*)(g_wbh + k*4096 + row*64 + ch*8);
            *(float4*)((char*)Wlo + row*144 + ch*16) =
                *(const float4*)(g_wbl + k*4096 + row*64 + ch*8);
        }
        // ---- sampling params ----
        if (tid < 128) {
            float dy = off[(2*k)*HWSZ + sp];
            float dx = off[(2*k+1)*HWSZ + sp];
            float m  = msk[k*HWSZ + sp];
            float yy = (float)(h - PADK + k/7) + dy;
            float xx = (float)(w - PADK + k%7) + dx;
            float y0f = floorf(yy), x0f = floorf(xx);
            float wy = yy - y0f, wx = xx - x0f;
            int y0 = (int)y0f, x0 = (int)x0f;
            int y1 = y0 + 1,   x1 = x0 + 1;
            bool vy0 = (y0 >= 0) && (y0 < HH), vy1 = (y1 >= 0) && (y1 < HH);
            bool vx0 = (x0 >= 0) && (x0 < WW), vx1 = (x1 >= 0) && (x1 < WW);
            int y0c = min(max(y0, 0), HH-1), y1c = min(max(y1, 0), HH-1);
            int x0c = min(max(x0, 0), WW-1), x1c = min(max(x1, 0), WW-1);
            sIdx[0*128 + tid] = (y0c*WW + x0c) * 64;
            sIdx[1*128 + tid] = (y0c*WW + x1c) * 64;
            sIdx[2*128 + tid] = (y1c*WW + x0c) * 64;
            sIdx[3*128 + tid] = (y1c*WW + x1c) * 64;
            sWt[0*128 + tid] = (vy0 && vx0) ? (1.f-wy)*(1.f-wx)*m : 0.f;
            sWt[1*128 + tid] = (vy0 && vx1) ? (1.f-wy)*wx*m       : 0.f;
            sWt[2*128 + tid] = (vy1 && vx0) ? wy*(1.f-wx)*m       : 0.f;
            sWt[3*128 + tid] = (vy1 && vx1) ? wy*wx*m             : 0.f;
        }
        __syncthreads();

        // ---- gather: bilinear fp32, split bf16 hi/lo into V[p][72] ----
        int c4 = tid & 15;
        #pragma unroll
        for (int it = 0; it < 2; it++) {
            int pq = (tid >> 4) + it * 16;
            int p0 = pq * 4;
            #pragma unroll
            for (int pp = 0; pp < 4; pp++) {
                int p = p0 + pp;
                const float4 t0 = *(const float4*)(encT + sIdx[0*128 + p] + (c4 << 2));
                const float4 t1 = *(const float4*)(encT + sIdx[1*128 + p] + (c4 << 2));
                const float4 t2 = *(const float4*)(encT + sIdx[2*128 + p] + (c4 << 2));
                const float4 t3 = *(const float4*)(encT + sIdx[3*128 + p] + (c4 << 2));
                float w0 = sWt[0*128 + p], w1 = sWt[1*128 + p];
                float w2 = sWt[2*128 + p], w3 = sWt[3*128 + p];
                float v0 = w0*t0.x + w1*t1.x + w2*t2.x + w3*t3.x;
                float v1 = w0*t0.y + w1*t1.y + w2*t2.y + w3*t3.y;
                float v2 = w0*t0.z + w1*t1.z + w2*t2.z + w3*t3.z;
                float v3 = w0*t0.w + w1*t1.w + w2*t2.w + w3*t3.w;
                uint32_t h01, h23, l01, l23;
                asm("cvt.rn.bf16x2.f32 %0, %1, %2;" : "=r"(h01) : "f"(v1), "f"(v0));
                asm("cvt.rn.bf16x2.f32 %0, %1, %2;" : "=r"(h23) : "f"(v3), "f"(v2));
                float hv0 = __uint_as_float(h01 << 16);
                float hv1 = __uint_as_float(h01 & 0xffff0000u);
                float hv2 = __uint_as_float(h23 << 16);
                float hv3 = __uint_as_float(h23 & 0xffff0000u);
                asm("cvt.rn.bf16x2.f32 %0, %1, %2;" : "=r"(l01) : "f"(v1 - hv1), "f"(v0 - hv0));
                asm("cvt.rn.bf16x2.f32 %0, %1, %2;" : "=r"(l23) : "f"(v3 - hv3), "f"(v2 - hv2));
                *(uint2*)((char*)Vhi + p*144 + c4*8) = make_uint2(h01, h23);
                *(uint2*)((char*)Vlo + p*144 + c4*8) = make_uint2(l01, l23);
            }
        }
        __syncthreads();

        // ---- WMMA: warp (mg, ng) owns px rows mg*32..+31, o cols ng*32..+31 ----
        #pragma unroll
        for (int kc = 0; kc < 4; kc++) {
            wmma::fragment<wmma::matrix_a, 16, 16, 16, __nv_bfloat16, wmma::row_major> ah[2], al[2];
            #pragma unroll
            for (int mf = 0; mf < 2; mf++) {
                wmma::load_matrix_sync(ah[mf], Vhi + (mg*32 + mf*16)*72 + kc*16, 72);
                wmma::load_matrix_sync(al[mf], Vlo + (mg*32 + mf*16)*72 + kc*16, 72);
            }
            #pragma unroll
            for (int nf = 0; nf < 2; nf++) {
                wmma::fragment<wmma::matrix_b, 16, 16, 16, __nv_bfloat16, wmma::col_major> bh, bl;
                wmma::load_matrix_sync(bh, Whi + (ng*32 + nf*16)*72 + kc*16, 72);
                wmma::load_matrix_sync(bl, Wlo + (ng*32 + nf*16)*72 + kc*16, 72);
                #pragma unroll
                for (int mf = 0; mf < 2; mf++) {
                    wmma::mma_sync(dfr[mf][nf], ah[mf], bh, dfr[mf][nf]);
                    wmma::mma_sync(dfr[mf][nf], al[mf], bh, dfr[mf][nf]);
                    wmma::mma_sync(dfr[mf][nf], ah[mf], bl, dfr[mf][nf]);
                }
            }
        }
        __syncthreads();
    }

    // ---- readout: frags -> smem D[128][68] -> g_rev NCHW ----
    float* Dsh = (float*)dsm;
    #pragma unroll
    for (int mf = 0; mf < 2; mf++)
        #pragma unroll
        for (int nf = 0; nf < 2; nf++)
            wmma::store_matrix_sync(Dsh + (mg*32 + mf*16)*68 + ng*32 + nf*16,
                                    dfr[mf][nf], 68, wmma::mem_row_major);
    __syncthreads();
    {
        int p = tid & 127;
        int hf = tid >> 7;
        int base = (ph + (p >> 4))*WW + pw + (p & 15);
        #pragma unroll
        for (int i = 0; i < 32; i++) {
            int o = hf*32 + i;
            g_rev[o*HWSZ + base] = Dsh[p*68 + o];
        }
    }
}

// ---------------- 1x1 conv on enc -> patch-major e2pm, 128 thr, 256 px ----------------
__global__ void __launch_bounds__(128) k_conv1x1pm(const float* __restrict__ enc) {
    __shared__ ull Wt[64*64];
    int tid = threadIdx.x;
    {
        const ulonglong2* src = (const ulonglong2*)g_wpit2;
        ulonglong2* dst = (ulonglong2*)Wt;
        #pragma unroll
        for (int i = 0; i < 16; i++) dst[tid + i*128] = src[tid + i*128];
    }
    __syncthreads();

    int base = blockIdx.x * 256;
    int p = base + (tid & 7) + (tid >> 3) * 16;
    int p2 = p + 8;

    ull acc[64];
    #pragma unroll
    for (int c = 0; c < 64; c++) acc[c] = 0ull;

    for (int j = 0; j < 64; j++) {
        ull v = pack2(enc[j*HWSZ + p], enc[j*HWSZ + p2]);
        const ulonglong2* wrow = (const ulonglong2*)(Wt + j*64);
        #pragma unroll
        for (int cc = 0; cc < 32; cc++) {
            ulonglong2 wv = wrow[cc];
            FMA2(acc[2*cc],   wv.x, v, acc[2*cc]);
            FMA2(acc[2*cc+1], wv.y, v, acc[2*cc+1]);
        }
    }

    int h = p / 192, w = p % 192;
    int q = (h & 7)*8 + (w & 7);
    int pat = (h >> 3)*24 + (w >> 3);
    #pragma unroll
    for (int c = 0; c < 64; c++)
        *(ull*)&g_e2pm[c*(64*576) + q*576 + pat] = acc[c];
}

// ---------------- per-patch circular conv as dense GEMM per channel ----------------
#define FFT_SMEM (50176 + 32768)

__global__ void __launch_bounds__(256, 2) k_fftgemm() {
    extern __shared__ char dsm[];
    float* Es = (float*)dsm;
    ull*   Wp = (ull*)(dsm + 50176);

    int tid = threadIdx.x;
    int lane = tid & 31;
    int c = blockIdx.x, pg = blockIdx.y;

    #pragma unroll
    for (int i = 0; i < 12; i++) {
        int f = i*256 + tid;
        int q = f / 48, r = f % 48;
        *(float4*)&Es[q*196 + r*4] =
            *(const float4*)&g_e2pm[c*(64*576) + q*576 + pg*192 + r*4];
    }
    #pragma unroll
    for (int i = 0; i < 16; i++) {
        int f = i*256 + tid;
        int q = f >> 6, p = f & 63;
        int idx = (((p >> 3) - (q >> 3)) & 7)*8 + (((p & 7) - (q & 7)) & 7);
        Wp[f] = packpair(g_gg[c*64 + idx]);
    }
    __syncthreads();

    int pbase = (tid >> 5) * 8;
    ull acc[8][3];
    #pragma unroll
    for (int o = 0; o < 8; o++)
        #pragma unroll
        for (int g = 0; g < 3; g++) acc[o][g] = 0ull;

    #pragma unroll 8
    for (int q = 0; q < 64; q++) {
        ull A0 = *(const ull*)&Es[q*196 + 0*64 + 2*lane];
        ull A1 = *(const ull*)&Es[q*196 + 1*64 + 2*lane];
        ull A2 = *(const ull*)&Es[q*196 + 2*64 + 2*lane];
        const ulonglong2* wp = (const ulonglong2*)(Wp + q*64 + pbase);
        ulonglong2 w01 = wp[0], w23 = wp[1], w45 = wp[2], w67 = wp[3];
        ull wv[8] = {w01.x, w01.y, w23.x, w23.y, w45.x, w45.y, w67.x, w67.y};
        #pragma unroll
        for (int o = 0; o < 8; o++) {
            FMA2(acc[o][0], wv[o], A0, acc[o][0]);
            FMA2(acc[o][1], wv[o], A1, acc[o][1]);
            FMA2(acc[o][2], wv[o], A2, acc[o][2]);
        }
    }

    float* dst = g_fft + c*HWSZ;
    #pragma unroll
    for (int o = 0; o < 8; o++) {
        int p = pbase + o;
        int py = p >> 3, px = p & 7;
        #pragma unroll
        for (int g = 0; g < 3; g++) {
            int pat = pg*192 + g*64 + 2*lane;
            float lo = __uint_as_float((unsigned int)(acc[o][g] & 0xffffffffull));
            float hi = __uint_as_float((unsigned int)(acc[o][g] >> 32));
            dst[((pat/24)*8 + py)*WW + (pat%24)*8 + px] = lo;
            pat++;
            dst[((pat/24)*8 + py)*WW + (pat%24)*8 + px] = hi;
        }
    }
}

// ---------------- 3x3 conv (pad 1), input = g_fft + g_rev, 16x8 tile ----------------
#define C3_SMEM (33792 + 32768)

__global__ void __launch_bounds__(256, 2) k_conv3() {
    extern __shared__ char dsm[];
    float* Vsh = (float*)dsm;
    ull*   Wp  = (ull*)(dsm + 33792);

    int tid = threadIdx.x;
    int lane = tid & 31;
    int ot = (tid >> 5) * 8;
    int ph = blockIdx.y * 8, pw = blockIdx.x * 16;

    ull acc[8][2];
    #pragma unroll
    for (int o = 0; o < 8; o++)
        #pragma unroll
        for (int pr = 0; pr < 2; pr++) acc[o][pr] = 0ull;

    for (int k = 0; k < 9; k++) {
        int dy = k/3 - 1, dx = k%3 - 1;
        {
            const ulonglong2* wsrc = (const ulonglong2*)(g_wc2t2 + k*4096);
            ulonglong2* wdst = (ulonglong2*)Wp;
            #pragma unroll
            for (int i = 0; i < 8; i++) wdst[tid + i*256] = wsrc[tid + i*256];
        }
        #pragma unroll
        for (int i = 0; i < 32; i++) {
            int e = i*256 + tid;
            int c = e >> 7, p = e & 127;
            int h = ph + (p >> 4) + dy, w = pw + (p & 15) + dx;
            bool ok = (h >= 0) && (h < HH) && (w >= 0) && (w < WW);
            int sp = h*WW + w;
            Vsh[c*132 + p] = ok ? (g_fft[c*HWSZ + sp] + g_rev[c*HWSZ + sp]) : 0.f;
        }
        __syncthreads();

        #pragma unroll 8
        for (int c = 0; c < 64; c++) {
            union { float4 f; ull u[2]; } A;
            A.f = *(const float4*)&Vsh[c*132 + 4*lane];
            const ulonglong2* wp = (const ulonglong2*)(Wp + c*64 + ot);
            ulonglong2 w01 = wp[0], w23 = wp[1], w45 = wp[2], w67 = wp[3];
            ull wv[8] = {w01.x, w01.y, w23.x, w23.y, w45.x, w45.y, w67.x, w67.y};
            #pragma unroll
            for (int o = 0; o < 8; o++) {
                FMA2(acc[o][0], wv[o], A.u[0], acc[o][0]);
                FMA2(acc[o][1], wv[o], A.u[1], acc[o][1]);
            }
        }
        __syncthreads();
    }

    #pragma unroll
    for (int o = 0; o < 8; o++) {
        float* orow = g_e3 + (ot + o)*HWSZ;
        #pragma unroll
        for (int pr = 0; pr < 2; pr++) {
            int p0 = 4*lane + pr*2;
            int py = p0 >> 4, px = p0 & 15;
            *(ull*)(orow + (ph + py)*WW + pw + px) = acc[o][pr];
        }
    }
}

// ---------------- merged proj(128->128) + SimpleGate, 16x8 tile, 2/SM ----------------
// smem: Va float[64][132] 33792 | Vb 33792 | Wf float[64*128] 32768
#define PG_VA 0
#define PG_VB 33792
#define PG_W  67584
#define PG_SMEM 100352

__global__ void __launch_bounds__(256, 2) k_projgate(const float* __restrict__ dec,
                                                     float* __restrict__ out) {
    extern __shared__ char dsm[];
    float* Va = (float*)(dsm + PG_VA);
    float* Vb = (float*)(dsm + PG_VB);
    float* Wf = (float*)(dsm + PG_W);

    int tid = threadIdx.x;
    int lane = tid & 31;
    int ot = (tid >> 5) * 8;
    int ph = blockIdx.y * 8, pw = blockIdx.x * 16;

    // stage Va (e3) and Vb (dec), plus stage-0 weights
    #pragma unroll
    for (int i = 0; i < 32; i++) {
        int e = i*256 + tid;
        int c = e >> 7, p = e & 127;
        int sp = (ph + (p >> 4))*WW + pw + (p & 15);
        Va[c*132 + p] = g_e3[c*HWSZ + sp];
        Vb[c*132 + p] = dec[c*HWSZ + sp];
    }
    #pragma unroll
    for (int i = 0; i < 8; i++)
        ((float4*)Wf)[i*256 + tid] = ((const float4*)g_wpT)[i*256 + tid];
    __syncthreads();

    ull a1[8][2], a2[8][2];
    #pragma unroll
    for (int o = 0; o < 8; o++)
        #pragma unroll
        for (int pr = 0; pr < 2; pr++) { a1[o][pr] = 0ull; a2[o][pr] = 0ull; }

    // stage 0: e3 channels (j 0..63), W rows 0..63
    #pragma unroll 4
    for (int c = 0; c < 64; c++) {
        union { float4 f; ull u[2]; } A;
        A.f = *(const float4*)&Va[c*132 + 4*lane];
        const float* wr = Wf + c*128;
        float4 wa = *(const float4*)(wr + ot);
        float4 wb = *(const float4*)(wr + ot + 4);
        float4 wc = *(const float4*)(wr + 64 + ot);
        float4 wd = *(const float4*)(wr + 64 + ot + 4);
        float w1v[8] = {wa.x, wa.y, wa.z, wa.w, wb.x, wb.y, wb.z, wb.w};
        float w2v[8] = {wc.x, wc.y, wc.z, wc.w, wd.x, wd.y, wd.z, wd.w};
        #pragma unroll
        for (int o = 0; o < 8; o++) {
            ull p1 = packpair(w1v[o]);
            ull p2 = packpair(w2v[o]);
            FMA2(a1[o][0], p1, A.u[0], a1[o][0]);
            FMA2(a1[o][1], p1, A.u[1], a1[o][1]);
            FMA2(a2[o][0], p2, A.u[0], a2[o][0]);
            FMA2(a2[o][1], p2, A.u[1], a2[o][1]);
        }
    }
    __syncthreads();
    // stage 1 weights: W rows 64..127
    #pragma unroll
    for (int i = 0; i < 8; i++)
        ((float4*)Wf)[i*256 + tid] = ((const float4*)(g_wpT + 64*128))[i*256 + tid];
    __syncthreads();

    #pragma unroll 4
    for (int c = 0; c < 64; c++) {
        union { float4 f; ull u[2]; } A;
        A.f = *(const float4*)&Vb[c*132 + 4*lane];
        const float* wr = Wf + c*128;
        float4 wa = *(const float4*)(wr + ot);
        float4 wb = *(const float4*)(wr + ot + 4);
        float4 wc = *(const float4*)(wr + 64 + ot);
        float4 wd = *(const float4*)(wr + 64 + ot + 4);
        float w1v[8] = {wa.x, wa.y, wa.z, wa.w, wb.x, wb.y, wb.z, wb.w};
        float w2v[8] = {wc.x, wc.y, wc.z, wc.w, wd.x, wd.y, wd.z, wd.w};
        #pragma unroll
        for (int o = 0; o < 8; o++) {
            ull p1 = packpair(w1v[o]);
            ull p2 = packpair(w2v[o]);
            FMA2(a1[o][0], p1, A.u[0], a1[o][0]);
            FMA2(a1[o][1], p1, A.u[1], a1[o][1]);
            FMA2(a2[o][0], p2, A.u[0], a2[o][0]);
            FMA2(a2[o][1], p2, A.u[1], a2[o][1]);
        }
    }

    // gate + write
    #pragma unroll
    for (int o = 0; o < 8; o++) {
        float* orow = out + (ot + o)*HWSZ;
        #pragma unroll
        for (int pr = 0; pr < 2; pr++) {
            int p0 = 4*lane + pr*2;
            int py = p0 >> 4, px = p0 & 15;
            ull r;
            MUL2(r, a1[o][pr], a2[o][pr]);
            *(ull*)(orow + (ph + py)*WW + pw + px) = r;
        }
    }
}

extern "C" void kernel_launch(void* const* d_in, const int* in_sizes, int n_in,
                              void* d_out, int out_size) {
    const float* enc  = (const float*)d_in[0];
    const float* dec  = (const float*)d_in[1];
    const float* ioff = (const float*)d_in[2];
    const float* iw   = (const float*)d_in[3];
    const float* wpi  = (const float*)d_in[4];
    const float* fftw = (const float*)d_in[5];
    const float* wpo  = (const float*)d_in[6];
    const float* wdef = (const float*)d_in[7];
    const float* wc1  = (const float*)d_in[8];
    const float* wc2  = (const float*)d_in[9];
    float* out = (float*)d_out;

    cudaFuncSetAttribute(k_deform_wmma, cudaFuncAttributeMaxDynamicSharedMemorySize, DW_SMEM);
    cudaFuncSetAttribute(k_fftgemm,     cudaFuncAttributeMaxDynamicSharedMemorySize, FFT_SMEM);
    cudaFuncSetAttribute(k_conv3,       cudaFuncAttributeMaxDynamicSharedMemorySize, C3_SMEM);
    cudaFuncSetAttribute(k_projgate,    cudaFuncAttributeMaxDynamicSharedMemorySize, PG_SMEM);

    dim3 gdef(12, 24);    // 16w x 8h tiles
    dim3 gfft(64, 3);

    k_transpose  <<<576, 256>>>(enc);
    k_prep_wbf   <<<(KTAPS*4096 + 255)/256, 256>>>(wc1, wdef);
    k_prep_g     <<<64, 64>>>(fftw);
    k_deform_wmma<<<gdef, 256, DW_SMEM>>>(ioff, iw);
    k_prep_tr    <<<144, 256>>>(wc2, wpo, wpi);
    k_conv1x1pm  <<<144, 128>>>(enc);
    k_fftgemm    <<<gfft, 256, FFT_SMEM>>>();
    k_conv3      <<<gdef, 256, C3_SMEM>>>();
    k_projgate   <<<gdef, 256, PG_SMEM>>>(dec, out);
}

// round 9
// speedup vs baseline: 1.2097x; 1.1196x over previous
#include <cuda_runtime.h>
#include <cuda_fp16.h>
#include <mma.h>
#include <cstdint>

using namespace nvcuda;

#define HH 192
#define WW 192
#define HWSZ (192*192)
#define CC 64
#define KTAPS 49
#define PADK 3

#define FMA2(d,a,b,c) asm("fma.rn.f32x2 %0, %1, %2, %3;" : "=l"(d) : "l"(a), "l"(b), "l"(c))
#define MUL2(d,a,b)   asm("mul.rn.f32x2 %0, %1, %2;" : "=l"(d) : "l"(a), "l"(b))

typedef unsigned long long ull;

__device__ __forceinline__ ull packpair(float v) {
    unsigned int u = __float_as_uint(v);
    return ((ull)u << 32) | u;
}
__device__ __forceinline__ ull pack2(float lo, float hi) {
    return ((ull)__float_as_uint(hi) << 32) | __float_as_uint(lo);
}

// ---------------- scratch (no allocs allowed) ----------------
__device__ float g_rev [CC*HWSZ];
__device__ float g_fft [CC*HWSZ];
__device__ float g_e3  [CC*HWSZ];
__device__ float g_encT[HWSZ*CC];        // NHWC
__device__ float g_e2pm[CC*64*576];      // [c][q=64][patch=576]
__device__ __half g_wfh[KTAPS*64*64];    // [k][o][c] fp16 hi
__device__ __half g_wfl[KTAPS*64*64];    // [k][o][c] fp16 lo
__device__ ull   g_wc2t2[9*64*64];       // [k][c][o] pairs
__device__ float g_wpT [128*128];        // [j128][o128] plain (proj weights)
__device__ ull   g_wpit2[64*64];         // [j][c] pairs
__device__ float g_gg  [64*64];          // [c][a*8+d]

// ---------------- precompute: FFT filter -> circular conv kernel ----------------
__global__ void k_prep_g(const float* __restrict__ fw) {
    int c = blockIdx.x;
    int t = threadIdx.x;
    int a = t >> 3, d = t & 7;
    const float ct[8] = {1.f, 0.70710678118654752f, 0.f, -0.70710678118654752f,
                        -1.f, -0.70710678118654752f, 0.f, 0.70710678118654752f};
    const float st[8] = {0.f, 0.70710678118654752f, 1.f, 0.70710678118654752f,
                         0.f, -0.70710678118654752f, -1.f, -0.70710678118654752f};
    const float* w = fw + c * 40;
    float re = 0.f;
    for (int u = 0; u < 8; u++) {
        float rp = w[u*5+0] + ((d & 1) ? -w[u*5+4] : w[u*5+4]);
        float ip = 0.f;
        #pragma unroll
        for (int v = 1; v <= 3; v++) {
            int vd = (v * d) & 7;
            rp += 2.f * w[u*5+v] * ct[vd];
            ip += 2.f * w[u*5+v] * st[vd];
        }
        int ua = (u * a) & 7;
        re += ct[ua] * rp - st[ua] * ip;
    }
    g_gg[c*64 + t] = re * (1.f/64.f);
}

// ---------------- precompute: fused deform weight -> fp16 hi/lo [k][o][c] ----------------
__global__ void k_prep_wf(const float* __restrict__ wc1, const float* __restrict__ wd) {
    int idx = blockIdx.x * blockDim.x + threadIdx.x;   // k*4096 + c*64 + o
    if (idx >= KTAPS*64*64) return;
    int o = idx & 63, c = (idx >> 6) & 63, k = idx >> 12;
    float s = 0.f;
    for (int m = 0; m < 64; m++)
        s += wc1[o*64 + m] * wd[(m*64 + c)*49 + k];
    __half hi = __float2half(s);
    float hv = __half2float(hi);
    __half lo = __float2half(s - hv);
    g_wfh[k*4096 + o*64 + c] = hi;
    g_wfl[k*4096 + o*64 + c] = lo;
}

// ---------------- precompute: weight transposes ----------------
__global__ void k_prep_tr(const float* __restrict__ wc2, const float* __restrict__ wpo,
                          const float* __restrict__ wpi) {
    int idx = blockIdx.x * blockDim.x + threadIdx.x;
    if (idx < 9*4096) {
        int o = idx & 63, c = (idx >> 6) & 63, k = idx >> 12;
        g_wc2t2[idx] = packpair(wc2[(o*64 + c)*9 + k]);
    }
    if (idx < 128*128) {                        // [j][o] <- wpo[o][j]
        int j = idx >> 7, o = idx & 127;
        g_wpT[idx] = wpo[o*128 + j];
    }
    if (idx < 4096) {
        int j = idx >> 6, c = idx & 63;
        g_wpit2[idx] = packpair(wpi[c*64 + j]);
    }
}

// ---------------- NCHW -> NHWC transpose of enc ----------------
__global__ void __launch_bounds__(256) k_transpose(const float* __restrict__ enc) {
    __shared__ float S[64][65];
    int tid = threadIdx.x;
    int p0 = blockIdx.x * 64;
    #pragma unroll
    for (int i = 0; i < 16; i++) {
        int e = i*256 + tid;
        S[e >> 6][e & 63] = enc[(e >> 6)*HWSZ + p0 + (e & 63)];
    }
    __syncthreads();
    #pragma unroll
    for (int i = 0; i < 16; i++) {
        int e = i*256 + tid;
        g_encT[p0*64 + e] = S[e & 63][e >> 6];
    }
}

// ---------------- deform conv via WMMA fp16 (A single, W hi/lo), 16x8 tile ----------------
// smem (bytes):
//   VF  [128 px][72 f16] stride 144B : 0..18432
//   WH  [64 o][72 f16]   stride 144B : 18432..27648
//   WL  27648..36864
//   SIDX 36864..38912   (int[4][128])
//   SWT  38912..40960   (float[4][128])
// readout reuses smem as float D[128][68] (34816 B)
#define DF_VF   0
#define DF_WH   18432
#define DF_WL   27648
#define DF_SIDX 36864
#define DF_SWT  38912
#define DF_SMEM 40960

__global__ void __launch_bounds__(256, 2) k_deform_wmma(const float* __restrict__ off,
                                                        const float* __restrict__ msk) {
    extern __shared__ char dsm[];
    __half* Vf = (__half*)(dsm + DF_VF);
    __half* Wh = (__half*)(dsm + DF_WH);
    __half* Wl = (__half*)(dsm + DF_WL);
    int*   sIdx = (int*)(dsm + DF_SIDX);
    float* sWt  = (float*)(dsm + DF_SWT);
    const float* encT = g_encT;

    int tid = threadIdx.x;
    int wid = tid >> 5;
    int mg = wid & 3, ng = wid >> 2;     // 4 m-groups x 2 n-groups
    int ph = blockIdx.y * 8, pw = blockIdx.x * 16;    // 16w x 8h tile, 128 px
    int ly = (tid & 127) >> 4, lx = tid & 15;
    int h = ph + ly, w = pw + lx;
    int sp = h * WW + w;

    wmma::fragment<wmma::accumulator, 16, 16, 16, float> dfr[2][2];
    #pragma unroll
    for (int mf = 0; mf < 2; mf++)
        #pragma unroll
        for (int nf = 0; nf < 2; nf++) wmma::fill_fragment(dfr[mf][nf], 0.f);

    for (int k = 0; k < KTAPS; k++) {
        // ---- stage W hi/lo: [o][c] global -> [o][72] smem ----
        #pragma unroll
        for (int i = 0; i < 2; i++) {
            int f = i*256 + tid;
            int row = f >> 3, ch = f & 7;
            *(float4*)((char*)Wh + row*144 + ch*16) =
                *(const float4*)(g_wfh + k*4096 + row*64 + ch*8);
            *(float4*)((char*)Wl + row*144 + ch*16) =
                *(const float4*)(g_wfl + k*4096 + row*64 + ch*8);
        }
        // ---- sampling params ----
        if (tid < 128) {
            float dy = off[(2*k)*HWSZ + sp];
            float dx = off[(2*k+1)*HWSZ + sp];
            float m  = msk[k*HWSZ + sp];
            float yy = (float)(h - PADK + k/7) + dy;
            float xx = (float)(w - PADK + k%7) + dx;
            float y0f = floorf(yy), x0f = floorf(xx);
            float wy = yy - y0f, wx = xx - x0f;
            int y0 = (int)y0f, x0 = (int)x0f;
            int y1 = y0 + 1,   x1 = x0 + 1;
            bool vy0 = (y0 >= 0) && (y0 < HH), vy1 = (y1 >= 0) && (y1 < HH);
            bool vx0 = (x0 >= 0) && (x0 < WW), vx1 = (x1 >= 0) && (x1 < WW);
            int y0c = min(max(y0, 0), HH-1), y1c = min(max(y1, 0), HH-1);
            int x0c = min(max(x0, 0), WW-1), x1c = min(max(x1, 0), WW-1);
            sIdx[0*128 + tid] = (y0c*WW + x0c) * 64;
            sIdx[1*128 + tid] = (y0c*WW + x1c) * 64;
            sIdx[2*128 + tid] = (y1c*WW + x0c) * 64;
            sIdx[3*128 + tid] = (y1c*WW + x1c) * 64;
            sWt[0*128 + tid] = (vy0 && vx0) ? (1.f-wy)*(1.f-wx)*m : 0.f;
            sWt[1*128 + tid] = (vy0 && vx1) ? (1.f-wy)*wx*m       : 0.f;
            sWt[2*128 + tid] = (vy1 && vx0) ? wy*(1.f-wx)*m       : 0.f;
            sWt[3*128 + tid] = (vy1 && vx1) ? wy*wx*m             : 0.f;
        }
        __syncthreads();

        // ---- gather: bilinear fp32 -> fp16 into V[p][72] ----
        int c4 = tid & 15;
        #pragma unroll
        for (int it = 0; it < 2; it++) {
            int pq = (tid >> 4) + it * 16;
            int p0 = pq * 4;
            #pragma unroll
            for (int pp = 0; pp < 4; pp++) {
                int p = p0 + pp;
                const float4 t0 = *(const float4*)(encT + sIdx[0*128 + p] + (c4 << 2));
                const float4 t1 = *(const float4*)(encT + sIdx[1*128 + p] + (c4 << 2));
                const float4 t2 = *(const float4*)(encT + sIdx[2*128 + p] + (c4 << 2));
                const float4 t3 = *(const float4*)(encT + sIdx[3*128 + p] + (c4 << 2));
                float w0 = sWt[0*128 + p], w1 = sWt[1*128 + p];
                float w2 = sWt[2*128 + p], w3 = sWt[3*128 + p];
                float v0 = w0*t0.x + w1*t1.x + w2*t2.x + w3*t3.x;
                float v1 = w0*t0.y + w1*t1.y + w2*t2.y + w3*t3.y;
                float v2 = w0*t0.z + w1*t1.z + w2*t2.z + w3*t3.z;
                float v3 = w0*t0.w + w1*t1.w + w2*t2.w + w3*t3.w;
                uint32_t h01, h23;
                asm("cvt.rn.f16x2.f32 %0, %1, %2;" : "=r"(h01) : "f"(v1), "f"(v0));
                asm("cvt.rn.f16x2.f32 %0, %1, %2;" : "=r"(h23) : "f"(v3), "f"(v2));
                *(uint2*)((char*)Vf + p*144 + c4*8) = make_uint2(h01, h23);
            }
        }
        __syncthreads();

        // ---- WMMA: warp (mg, ng) owns px rows mg*32..+31, o cols ng*32..+31 ----
        #pragma unroll
        for (int kc = 0; kc < 4; kc++) {
            wmma::fragment<wmma::matrix_a, 16, 16, 16, __half, wmma::row_major> af[2];
            #pragma unroll
            for (int mf = 0; mf < 2; mf++)
                wmma::load_matrix_sync(af[mf], Vf + (mg*32 + mf*16)*72 + kc*16, 72);
            #pragma unroll
            for (int nf = 0; nf < 2; nf++) {
                wmma::fragment<wmma::matrix_b, 16, 16, 16, __half, wmma::col_major> bh, bl;
                wmma::load_matrix_sync(bh, Wh + (ng*32 + nf*16)*72 + kc*16, 72);
                wmma::load_matrix_sync(bl, Wl + (ng*32 + nf*16)*72 + kc*16, 72);
                #pragma unroll
                for (int mf = 0; mf < 2; mf++) {
                    wmma::mma_sync(dfr[mf][nf], af[mf], bh, dfr[mf][nf]);
                    wmma::mma_sync(dfr[mf][nf], af[mf], bl, dfr[mf][nf]);
                }
            }
        }
        __syncthreads();
    }

    // ---- readout: frags -> smem D[128][68] -> g_rev NCHW ----
    float* Dsh = (float*)dsm;
    #pragma unroll
    for (int mf = 0; mf < 2; mf++)
        #pragma unroll
        for (int nf = 0; nf < 2; nf++)
            wmma::store_matrix_sync(Dsh + (mg*32 + mf*16)*68 + ng*32 + nf*16,
                                    dfr[mf][nf], 68, wmma::mem_row_major);
    __syncthreads();
    {
        int p = tid & 127;
        int hf = tid >> 7;
        int base = (ph + (p >> 4))*WW + pw + (p & 15);
        #pragma unroll
        for (int i = 0; i < 32; i++) {
            int o = hf*32 + i;
            g_rev[o*HWSZ + base] = Dsh[p*68 + o];
        }
    }
}

// ---------------- 1x1 conv on enc -> patch-major e2pm, 128 thr, 256 px ----------------
__global__ void __launch_bounds__(128) k_conv1x1pm(const float* __restrict__ enc) {
    __shared__ ull Wt[64*64];
    int tid = threadIdx.x;
    {
        const ulonglong2* src = (const ulonglong2*)g_wpit2;
        ulonglong2* dst = (ulonglong2*)Wt;
        #pragma unroll
        for (int i = 0; i < 16; i++) dst[tid + i*128] = src[tid + i*128];
    }
    __syncthreads();

    int base = blockIdx.x * 256;
    int p = base + (tid & 7) + (tid >> 3) * 16;
    int p2 = p + 8;

    ull acc[64];
    #pragma unroll
    for (int c = 0; c < 64; c++) acc[c] = 0ull;

    for (int j = 0; j < 64; j++) {
        ull v = pack2(enc[j*HWSZ + p], enc[j*HWSZ + p2]);
        const ulonglong2* wrow = (const ulonglong2*)(Wt + j*64);
        #pragma unroll
        for (int cc = 0; cc < 32; cc++) {
            ulonglong2 wv = wrow[cc];
            FMA2(acc[2*cc],   wv.x, v, acc[2*cc]);
            FMA2(acc[2*cc+1], wv.y, v, acc[2*cc+1]);
        }
    }

    int h = p / 192, w = p % 192;
    int q = (h & 7)*8 + (w & 7);
    int pat = (h >> 3)*24 + (w >> 3);
    #pragma unroll
    for (int c = 0; c < 64; c++)
        *(ull*)&g_e2pm[c*(64*576) + q*576 + pat] = acc[c];
}

// ---------------- per-patch circular conv as dense GEMM per channel ----------------
#define FFT_SMEM (50176 + 32768)

__global__ void __launch_bounds__(256, 2) k_fftgemm() {
    extern __shared__ char dsm[];
    float* Es = (float*)dsm;
    ull*   Wp = (ull*)(dsm + 50176);

    int tid = threadIdx.x;
    int lane = tid & 31;
    int c = blockIdx.x, pg = blockIdx.y;

    #pragma unroll
    for (int i = 0; i < 12; i++) {
        int f = i*256 + tid;
        int q = f / 48, r = f % 48;
        *(float4*)&Es[q*196 + r*4] =
            *(const float4*)&g_e2pm[c*(64*576) + q*576 + pg*192 + r*4];
    }
    #pragma unroll
    for (int i = 0; i < 16; i++) {
        int f = i*256 + tid;
        int q = f >> 6, p = f & 63;
        int idx = (((p >> 3) - (q >> 3)) & 7)*8 + (((p & 7) - (q & 7)) & 7);
        Wp[f] = packpair(g_gg[c*64 + idx]);
    }
    __syncthreads();

    int pbase = (tid >> 5) * 8;
    ull acc[8][3];
    #pragma unroll
    for (int o = 0; o < 8; o++)
        #pragma unroll
        for (int g = 0; g < 3; g++) acc[o][g] = 0ull;

    #pragma unroll 8
    for (int q = 0; q < 64; q++) {
        ull A0 = *(const ull*)&Es[q*196 + 0*64 + 2*lane];
        ull A1 = *(const ull*)&Es[q*196 + 1*64 + 2*lane];
        ull A2 = *(const ull*)&Es[q*196 + 2*64 + 2*lane];
        const ulonglong2* wp = (const ulonglong2*)(Wp + q*64 + pbase);
        ulonglong2 w01 = wp[0], w23 = wp[1], w45 = wp[2], w67 = wp[3];
        ull wv[8] = {w01.x, w01.y, w23.x, w23.y, w45.x, w45.y, w67.x, w67.y};
        #pragma unroll
        for (int o = 0; o < 8; o++) {
            FMA2(acc[o][0], wv[o], A0, acc[o][0]);
            FMA2(acc[o][1], wv[o], A1, acc[o][1]);
            FMA2(acc[o][2], wv[o], A2, acc[o][2]);
        }
    }

    float* dst = g_fft + c*HWSZ;
    #pragma unroll
    for (int o = 0; o < 8; o++) {
        int p = pbase + o;
        int py = p >> 3, px = p & 7;
        #pragma unroll
        for (int g = 0; g < 3; g++) {
            int pat = pg*192 + g*64 + 2*lane;
            float lo = __uint_as_float((unsigned int)(acc[o][g] & 0xffffffffull));
            float hi = __uint_as_float((unsigned int)(acc[o][g] >> 32));
            dst[((pat/24)*8 + py)*WW + (pat%24)*8 + px] = lo;
            pat++;
            dst[((pat/24)*8 + py)*WW + (pat%24)*8 + px] = hi;
        }
    }
}

// ---------------- 3x3 conv (pad 1), input = g_fft + g_rev, 16x8 tile ----------------
#define C3_SMEM (33792 + 32768)

__global__ void __launch_bounds__(256, 2) k_conv3() {
    extern __shared__ char dsm[];
    float* Vsh = (float*)dsm;
    ull*   Wp  = (ull*)(dsm + 33792);

    int tid = threadIdx.x;
    int lane = tid & 31;
    int ot = (tid >> 5) * 8;
    int ph = blockIdx.y * 8, pw = blockIdx.x * 16;

    ull acc[8][2];
    #pragma unroll
    for (int o = 0; o < 8; o++)
        #pragma unroll
        for (int pr = 0; pr < 2; pr++) acc[o][pr] = 0ull;

    for (int k = 0; k < 9; k++) {
        int dy = k/3 - 1, dx = k%3 - 1;
        {
            const ulonglong2* wsrc = (const ulonglong2*)(g_wc2t2 + k*4096);
            ulonglong2* wdst = (ulonglong2*)Wp;
            #pragma unroll
            for (int i = 0; i < 8; i++) wdst[tid + i*256] = wsrc[tid + i*256];
        }
        #pragma unroll
        for (int i = 0; i < 32; i++) {
            int e = i*256 + tid;
            int c = e >> 7, p = e & 127;
            int h = ph + (p >> 4) + dy, w = pw + (p & 15) + dx;
            bool ok = (h >= 0) && (h < HH) && (w >= 0) && (w < WW);
            int sp = h*WW + w;
            Vsh[c*132 + p] = ok ? (g_fft[c*HWSZ + sp] + g_rev[c*HWSZ + sp]) : 0.f;
        }
        __syncthreads();

        #pragma unroll 8
        for (int c = 0; c < 64; c++) {
            union { float4 f; ull u[2]; } A;
            A.f = *(const float4*)&Vsh[c*132 + 4*lane];
            const ulonglong2* wp = (const ulonglong2*)(Wp + c*64 + ot);
            ulonglong2 w01 = wp[0], w23 = wp[1], w45 = wp[2], w67 = wp[3];
            ull wv[8] = {w01.x, w01.y, w23.x, w23.y, w45.x, w45.y, w67.x, w67.y};
            #pragma unroll
            for (int o = 0; o < 8; o++) {
                FMA2(acc[o][0], wv[o], A.u[0], acc[o][0]);
                FMA2(acc[o][1], wv[o], A.u[1], acc[o][1]);
            }
        }
        __syncthreads();
    }

    #pragma unroll
    for (int o = 0; o < 8; o++) {
        float* orow = g_e3 + (ot + o)*HWSZ;
        #pragma unroll
        for (int pr = 0; pr < 2; pr++) {
            int p0 = 4*lane + pr*2;
            int py = p0 >> 4, px = p0 & 15;
            *(ull*)(orow + (ph + py)*WW + pw + px) = acc[o][pr];
        }
    }
}

// ---------------- merged proj(128->128) + SimpleGate, 16x8 tile, 2/SM ----------------
#define PG_VA 0
#define PG_VB 33792
#define PG_W  67584
#define PG_SMEM 100352

__global__ void __launch_bounds__(256, 2) k_projgate(const float* __restrict__ dec,
                                                     float* __restrict__ out) {
    extern __shared__ char dsm[];
    float* Va = (float*)(dsm + PG_VA);
    float* Vb = (float*)(dsm + PG_VB);
    float* Wf = (float*)(dsm + PG_W);

    int tid = threadIdx.x;
    int lane = tid & 31;
    int ot = (tid >> 5) * 8;
    int ph = blockIdx.y * 8, pw = blockIdx.x * 16;

    #pragma unroll
    for (int i = 0; i < 32; i++) {
        int e = i*256 + tid;
        int c = e >> 7, p = e & 127;
        int sp = (ph + (p >> 4))*WW + pw + (p & 15);
        Va[c*132 + p] = g_e3[c*HWSZ + sp];
        Vb[c*132 + p] = dec[c*HWSZ + sp];
    }
    #pragma unroll
    for (int i = 0; i < 8; i++)
        ((float4*)Wf)[i*256 + tid] = ((const float4*)g_wpT)[i*256 + tid];
    __syncthreads();

    ull a1[8][2], a2[8][2];
    #pragma unroll
    for (int o = 0; o < 8; o++)
        #pragma unroll
        for (int pr = 0; pr < 2; pr++) { a1[o][pr] = 0ull; a2[o][pr] = 0ull; }

    #pragma unroll 4
    for (int c = 0; c < 64; c++) {
        union { float4 f; ull u[2]; } A;
        A.f = *(const float4*)&Va[c*132 + 4*lane];
        const float* wr = Wf + c*128;
        float4 wa = *(const float4*)(wr + ot);
        float4 wb = *(const float4*)(wr + ot + 4);
        float4 wc = *(const float4*)(wr + 64 + ot);
        float4 wd = *(const float4*)(wr + 64 + ot + 4);
        float w1v[8] = {wa.x, wa.y, wa.z, wa.w, wb.x, wb.y, wb.z, wb.w};
        float w2v[8] = {wc.x, wc.y, wc.z, wc.w, wd.x, wd.y, wd.z, wd.w};
        #pragma unroll
        for (int o = 0; o < 8; o++) {
            ull p1 = packpair(w1v[o]);
            ull p2 = packpair(w2v[o]);
            FMA2(a1[o][0], p1, A.u[0], a1[o][0]);
            FMA2(a1[o][1], p1, A.u[1], a1[o][1]);
            FMA2(a2[o][0], p2, A.u[0], a2[o][0]);
            FMA2(a2[o][1], p2, A.u[1], a2[o][1]);
        }
    }
    __syncthreads();
    #pragma unroll
    for (int i = 0; i < 8; i++)
        ((float4*)Wf)[i*256 + tid] = ((const float4*)(g_wpT + 64*128))[i*256 + tid];
    __syncthreads();

    #pragma unroll 4
    for (int c = 0; c < 64; c++) {
        union { float4 f; ull u[2]; } A;
        A.f = *(const float4*)&Vb[c*132 + 4*lane];
        const float* wr = Wf + c*128;
        float4 wa = *(const float4*)(wr + ot);
        float4 wb = *(const float4*)(wr + ot + 4);
        float4 wc = *(const float4*)(wr + 64 + ot);
        float4 wd = *(const float4*)(wr + 64 + ot + 4);
        float w1v[8] = {wa.x, wa.y, wa.z, wa.w, wb.x, wb.y, wb.z, wb.w};
        float w2v[8] = {wc.x, wc.y, wc.z, wc.w, wd.x, wd.y, wd.z, wd.w};
        #pragma unroll
        for (int o = 0; o < 8; o++) {
            ull p1 = packpair(w1v[o]);
            ull p2 = packpair(w2v[o]);
            FMA2(a1[o][0], p1, A.u[0], a1[o][0]);
            FMA2(a1[o][1], p1, A.u[1], a1[o][1]);
            FMA2(a2[o][0], p2, A.u[0], a2[o][0]);
            FMA2(a2[o][1], p2, A.u[1], a2[o][1]);
        }
    }

    #pragma unroll
    for (int o = 0; o < 8; o++) {
        float* orow = out + (ot + o)*HWSZ;
        #pragma unroll
        for (int pr = 0; pr < 2; pr++) {
            int p0 = 4*lane + pr*2;
            int py = p0 >> 4, px = p0 & 15;
            ull r;
            MUL2(r, a1[o][pr], a2[o][pr]);
            *(ull*)(orow + (ph + py)*WW + pw + px) = r;
        }
    }
}

extern "C" void kernel_launch(void* const* d_in, const int* in_sizes, int n_in,
                              void* d_out, int out_size) {
    const float* enc  = (const float*)d_in[0];
    const float* dec  = (const float*)d_in[1];
    const float* ioff = (const float*)d_in[2];
    const float* iw   = (const float*)d_in[3];
    const float* wpi  = (const float*)d_in[4];
    const float* fftw = (const float*)d_in[5];
    const float* wpo  = (const float*)d_in[6];
    const float* wdef = (const float*)d_in[7];
    const float* wc1  = (const float*)d_in[8];
    const float* wc2  = (const float*)d_in[9];
    float* out = (float*)d_out;

    cudaFuncSetAttribute(k_deform_wmma, cudaFuncAttributeMaxDynamicSharedMemorySize, DF_SMEM);
    cudaFuncSetAttribute(k_fftgemm,     cudaFuncAttributeMaxDynamicSharedMemorySize, FFT_SMEM);
    cudaFuncSetAttribute(k_conv3,       cudaFuncAttributeMaxDynamicSharedMemorySize, C3_SMEM);
    cudaFuncSetAttribute(k_projgate,    cudaFuncAttributeMaxDynamicSharedMemorySize, PG_SMEM);

    dim3 gdef(12, 24);    // 16w x 8h tiles
    dim3 gfft(64, 3);

    k_transpose  <<<576, 256>>>(enc);
    k_prep_wf    <<<(KTAPS*4096 + 255)/256, 256>>>(wc1, wdef);
    k_prep_g     <<<64, 64>>>(fftw);
    k_deform_wmma<<<gdef, 256, DF_SMEM>>>(ioff, iw);
    k_prep_tr    <<<144, 256>>>(wc2, wpo, wpi);
    k_conv1x1pm  <<<144, 128>>>(enc);
    k_fftgemm    <<<gfft, 256, FFT_SMEM>>>();
    k_conv3      <<<gdef, 256, C3_SMEM>>>();
    k_projgate   <<<gdef, 256, PG_SMEM>>>(dec, out);
}

// round 10
// speedup vs baseline: 1.3229x; 1.0936x over previous
#include <cuda_runtime.h>
#include <cuda_fp16.h>
#include <mma.h>
#include <cstdint>

using namespace nvcuda;

#define HH 192
#define WW 192
#define HWSZ (192*192)
#define CC 64
#define KTAPS 49
#define PADK 3

#define FMA2(d,a,b,c) asm("fma.rn.f32x2 %0, %1, %2, %3;" : "=l"(d) : "l"(a), "l"(b), "l"(c))
#define MUL2(d,a,b)   asm("mul.rn.f32x2 %0, %1, %2;" : "=l"(d) : "l"(a), "l"(b))

typedef unsigned long long ull;

__device__ __forceinline__ ull packpair(float v) {
    unsigned int u = __float_as_uint(v);
    return ((ull)u << 32) | u;
}
__device__ __forceinline__ ull pack2(float lo, float hi) {
    return ((ull)__float_as_uint(hi) << 32) | __float_as_uint(lo);
}

// ---------------- scratch (no allocs allowed) ----------------
__device__ float  g_rev [CC*HWSZ];
__device__ float  g_fft [CC*HWSZ];
__device__ float  g_e3  [CC*HWSZ];
__device__ __half g_encTh[HWSZ*CC];       // NHWC fp16
__device__ float  g_e2pm[CC*64*576];      // [c][q=64][patch=576]
__device__ __half g_wfh[KTAPS*64*64];     // [k][o][c] fp16
__device__ ull    g_wc2t2[9*64*64];       // [k][c][o] pairs
__device__ float  g_wpT [128*128];        // [j128][o128] plain (proj weights)
__device__ ull    g_wpit2[64*64];         // [j][c] pairs
__device__ float  g_gg  [64*64];          // [c][a*8+d]

// ---------------- precompute: FFT filter -> circular conv kernel ----------------
__global__ void k_prep_g(const float* __restrict__ fw) {
    int c = blockIdx.x;
    int t = threadIdx.x;
    int a = t >> 3, d = t & 7;
    const float ct[8] = {1.f, 0.70710678118654752f, 0.f, -0.70710678118654752f,
                        -1.f, -0.70710678118654752f, 0.f, 0.70710678118654752f};
    const float st[8] = {0.f, 0.70710678118654752f, 1.f, 0.70710678118654752f,
                         0.f, -0.70710678118654752f, -1.f, -0.70710678118654752f};
    const float* w = fw + c * 40;
    float re = 0.f;
    for (int u = 0; u < 8; u++) {
        float rp = w[u*5+0] + ((d & 1) ? -w[u*5+4] : w[u*5+4]);
        float ip = 0.f;
        #pragma unroll
        for (int v = 1; v <= 3; v++) {
            int vd = (v * d) & 7;
            rp += 2.f * w[u*5+v] * ct[vd];
            ip += 2.f * w[u*5+v] * st[vd];
        }
        int ua = (u * a) & 7;
        re += ct[ua] * rp - st[ua] * ip;
    }
    g_gg[c*64 + t] = re * (1.f/64.f);
}

// ---------------- precompute: fused deform weight -> fp16 [k][o][c] ----------------
__global__ void k_prep_wf(const float* __restrict__ wc1, const float* __restrict__ wd) {
    int idx = blockIdx.x * blockDim.x + threadIdx.x;   // k*4096 + c*64 + o
    if (idx >= KTAPS*64*64) return;
    int o = idx & 63, c = (idx >> 6) & 63, k = idx >> 12;
    float s = 0.f;
    for (int m = 0; m < 64; m++)
        s += wc1[o*64 + m] * wd[(m*64 + c)*49 + k];
    g_wfh[k*4096 + o*64 + c] = __float2half(s);
}

// ---------------- precompute: weight transposes ----------------
__global__ void k_prep_tr(const float* __restrict__ wc2, const float* __restrict__ wpo,
                          const float* __restrict__ wpi) {
    int idx = blockIdx.x * blockDim.x + threadIdx.x;
    if (idx < 9*4096) {
        int o = idx & 63, c = (idx >> 6) & 63, k = idx >> 12;
        g_wc2t2[idx] = packpair(wc2[(o*64 + c)*9 + k]);
    }
    if (idx < 128*128) {                        // [j][o] <- wpo[o][j]
        int j = idx >> 7, o = idx & 127;
        g_wpT[idx] = wpo[o*128 + j];
    }
    if (idx < 4096) {
        int j = idx >> 6, c = idx & 63;
        g_wpit2[idx] = packpair(wpi[c*64 + j]);
    }
}

// ---------------- NCHW -> NHWC fp16 transpose of enc ----------------
__global__ void __launch_bounds__(256) k_transpose(const float* __restrict__ enc) {
    __shared__ float S[64][65];
    int tid = threadIdx.x;
    int p0 = blockIdx.x * 64;
    #pragma unroll
    for (int i = 0; i < 16; i++) {
        int e = i*256 + tid;
        S[e >> 6][e & 63] = enc[(e >> 6)*HWSZ + p0 + (e & 63)];
    }
    __syncthreads();
    #pragma unroll
    for (int i = 0; i < 8; i++) {
        int e2 = i*512 + tid*2;          // pairs: e2 = lp*64 + c (c even)
        int lp = e2 >> 6, c = e2 & 63;
        __half2 hp = __floats2half2_rn(S[c][lp], S[c+1][lp]);
        *(__half2*)&g_encTh[p0*64 + e2] = hp;
    }
}

// ---------------- deform conv via WMMA fp16 (A fp16-enc gather, W single), 16x8 tile ----------------
// smem (bytes):
//   VF  [128 px][72 f16] stride 144B : 0..18432
//   WH  [64 o][72 f16]   stride 144B : 18432..27648
//   SIDX 27648..29696   (int[4][128])
//   SWT  29696..31744   (float[4][128])
// readout reuses smem as float D[128][68] (34816 B) -> DF_SMEM = 36864
#define DF_VF   0
#define DF_WH   18432
#define DF_SIDX 27648
#define DF_SWT  29696
#define DF_SMEM 36864

__global__ void __launch_bounds__(256, 2) k_deform_wmma(const float* __restrict__ off,
                                                        const float* __restrict__ msk) {
    extern __shared__ char dsm[];
    __half* Vf = (__half*)(dsm + DF_VF);
    __half* Wh = (__half*)(dsm + DF_WH);
    int*   sIdx = (int*)(dsm + DF_SIDX);
    float* sWt  = (float*)(dsm + DF_SWT);
    const __half* encT = g_encTh;

    int tid = threadIdx.x;
    int wid = tid >> 5;
    int mg = wid & 3, ng = wid >> 2;     // 4 m-groups x 2 n-groups
    int ph = blockIdx.y * 8, pw = blockIdx.x * 16;    // 16w x 8h tile, 128 px
    int ly = (tid & 127) >> 4, lx = tid & 15;
    int h = ph + ly, w = pw + lx;
    int sp = h * WW + w;

    wmma::fragment<wmma::accumulator, 16, 16, 16, float> dfr[2][2];
    #pragma unroll
    for (int mf = 0; mf < 2; mf++)
        #pragma unroll
        for (int nf = 0; nf < 2; nf++) wmma::fill_fragment(dfr[mf][nf], 0.f);

    for (int k = 0; k < KTAPS; k++) {
        // ---- stage W: [o][c] global -> [o][72] smem ----
        #pragma unroll
        for (int i = 0; i < 2; i++) {
            int f = i*256 + tid;          // 0..511 : row = f>>3, chunk = f&7
            int row = f >> 3, ch = f & 7;
            *(float4*)((char*)Wh + row*144 + ch*16) =
                *(const float4*)(g_wfh + k*4096 + row*64 + ch*8);
        }
        // ---- sampling params ----
        if (tid < 128) {
            float dy = off[(2*k)*HWSZ + sp];
            float dx = off[(2*k+1)*HWSZ + sp];
            float m  = msk[k*HWSZ + sp];
            float yy = (float)(h - PADK + k/7) + dy;
            float xx = (float)(w - PADK + k%7) + dx;
            float y0f = floorf(yy), x0f = floorf(xx);
            float wy = yy - y0f, wx = xx - x0f;
            int y0 = (int)y0f, x0 = (int)x0f;
            int y1 = y0 + 1,   x1 = x0 + 1;
            bool vy0 = (y0 >= 0) && (y0 < HH), vy1 = (y1 >= 0) && (y1 < HH);
            bool vx0 = (x0 >= 0) && (x0 < WW), vx1 = (x1 >= 0) && (x1 < WW);
            int y0c = min(max(y0, 0), HH-1), y1c = min(max(y1, 0), HH-1);
            int x0c = min(max(x0, 0), WW-1), x1c = min(max(x1, 0), WW-1);
            sIdx[0*128 + tid] = (y0c*WW + x0c) * 64;
            sIdx[1*128 + tid] = (y0c*WW + x1c) * 64;
            sIdx[2*128 + tid] = (y1c*WW + x0c) * 64;
            sIdx[3*128 + tid] = (y1c*WW + x1c) * 64;
            sWt[0*128 + tid] = (vy0 && vx0) ? (1.f-wy)*(1.f-wx)*m : 0.f;
            sWt[1*128 + tid] = (vy0 && vx1) ? (1.f-wy)*wx*m       : 0.f;
            sWt[2*128 + tid] = (vy1 && vx0) ? wy*(1.f-wx)*m       : 0.f;
            sWt[3*128 + tid] = (vy1 && vx1) ? wy*wx*m             : 0.f;
        }
        __syncthreads();

        // ---- gather: fp16 loads, bilinear fp32 -> fp16 into V[p][72] ----
        int c4 = tid & 15;
        #pragma unroll
        for (int it = 0; it < 2; it++) {
            int pq = (tid >> 4) + it * 16;
            int p0 = pq * 4;
            #pragma unroll
            for (int pp = 0; pp < 4; pp++) {
                int p = p0 + pp;
                uint2 q0 = *(const uint2*)(encT + sIdx[0*128 + p] + (c4 << 2));
                uint2 q1 = *(const uint2*)(encT + sIdx[1*128 + p] + (c4 << 2));
                uint2 q2 = *(const uint2*)(encT + sIdx[2*128 + p] + (c4 << 2));
                uint2 q3 = *(const uint2*)(encT + sIdx[3*128 + p] + (c4 << 2));
                float2 a0 = __half22float2(*(__half2*)&q0.x);
                float2 b0 = __half22float2(*(__half2*)&q0.y);
                float2 a1 = __half22float2(*(__half2*)&q1.x);
                float2 b1 = __half22float2(*(__half2*)&q1.y);
                float2 a2 = __half22float2(*(__half2*)&q2.x);
                float2 b2 = __half22float2(*(__half2*)&q2.y);
                float2 a3 = __half22float2(*(__half2*)&q3.x);
                float2 b3 = __half22float2(*(__half2*)&q3.y);
                float w0 = sWt[0*128 + p], w1 = sWt[1*128 + p];
                float w2 = sWt[2*128 + p], w3 = sWt[3*128 + p];
                float v0 = w0*a0.x + w1*a1.x + w2*a2.x + w3*a3.x;
                float v1 = w0*a0.y + w1*a1.y + w2*a2.y + w3*a3.y;
                float v2 = w0*b0.x + w1*b1.x + w2*b2.x + w3*b3.x;
                float v3 = w0*b0.y + w1*b1.y + w2*b2.y + w3*b3.y;
                uint32_t h01, h23;
                asm("cvt.rn.f16x2.f32 %0, %1, %2;" : "=r"(h01) : "f"(v1), "f"(v0));
                asm("cvt.rn.f16x2.f32 %0, %1, %2;" : "=r"(h23) : "f"(v3), "f"(v2));
                *(uint2*)((char*)Vf + p*144 + c4*8) = make_uint2(h01, h23);
            }
        }
        __syncthreads();

        // ---- WMMA: warp (mg, ng) owns px rows mg*32..+31, o cols ng*32..+31 ----
        #pragma unroll
        for (int kc = 0; kc < 4; kc++) {
            wmma::fragment<wmma::matrix_a, 16, 16, 16, __half, wmma::row_major> af[2];
            #pragma unroll
            for (int mf = 0; mf < 2; mf++)
                wmma::load_matrix_sync(af[mf], Vf + (mg*32 + mf*16)*72 + kc*16, 72);
            #pragma unroll
            for (int nf = 0; nf < 2; nf++) {
                wmma::fragment<wmma::matrix_b, 16, 16, 16, __half, wmma::col_major> bh;
                wmma::load_matrix_sync(bh, Wh + (ng*32 + nf*16)*72 + kc*16, 72);
                #pragma unroll
                for (int mf = 0; mf < 2; mf++)
                    wmma::mma_sync(dfr[mf][nf], af[mf], bh, dfr[mf][nf]);
            }
        }
        __syncthreads();
    }

    // ---- readout: frags -> smem D[128][68] -> g_rev NCHW ----
    float* Dsh = (float*)dsm;
    #pragma unroll
    for (int mf = 0; mf < 2; mf++)
        #pragma unroll
        for (int nf = 0; nf < 2; nf++)
            wmma::store_matrix_sync(Dsh + (mg*32 + mf*16)*68 + ng*32 + nf*16,
                                    dfr[mf][nf], 68, wmma::mem_row_major);
    __syncthreads();
    {
        int p = tid & 127;
        int hf = tid >> 7;
        int base = (ph + (p >> 4))*WW + pw + (p & 15);
        #pragma unroll
        for (int i = 0; i < 32; i++) {
            int o = hf*32 + i;
            g_rev[o*HWSZ + base] = Dsh[p*68 + o];
        }
    }
}

// ---------------- 1x1 conv on enc -> patch-major e2pm, 128 thr, 256 px ----------------
__global__ void __launch_bounds__(128) k_conv1x1pm(const float* __restrict__ enc) {
    __shared__ ull Wt[64*64];
    int tid = threadIdx.x;
    {
        const ulonglong2* src = (const ulonglong2*)g_wpit2;
        ulonglong2* dst = (ulonglong2*)Wt;
        #pragma unroll
        for (int i = 0; i < 16; i++) dst[tid + i*128] = src[tid + i*128];
    }
    __syncthreads();

    int base = blockIdx.x * 256;
    int p = base + (tid & 7) + (tid >> 3) * 16;
    int p2 = p + 8;

    ull acc[64];
    #pragma unroll
    for (int c = 0; c < 64; c++) acc[c] = 0ull;

    for (int j = 0; j < 64; j++) {
        ull v = pack2(enc[j*HWSZ + p], enc[j*HWSZ + p2]);
        const ulonglong2* wrow = (const ulonglong2*)(Wt + j*64);
        #pragma unroll
        for (int cc = 0; cc < 32; cc++) {
            ulonglong2 wv = wrow[cc];
            FMA2(acc[2*cc],   wv.x, v, acc[2*cc]);
            FMA2(acc[2*cc+1], wv.y, v, acc[2*cc+1]);
        }
    }

    int h = p / 192, w = p % 192;
    int q = (h & 7)*8 + (w & 7);
    int pat = (h >> 3)*24 + (w >> 3);
    #pragma unroll
    for (int c = 0; c < 64; c++)
        *(ull*)&g_e2pm[c*(64*576) + q*576 + pat] = acc[c];
}

// ---------------- per-patch circular conv as dense GEMM per channel ----------------
#define FFT_SMEM (50176 + 32768)

__global__ void __launch_bounds__(256, 2) k_fftgemm() {
    extern __shared__ char dsm[];
    float* Es = (float*)dsm;
    ull*   Wp = (ull*)(dsm + 50176);

    int tid = threadIdx.x;
    int lane = tid & 31;
    int c = blockIdx.x, pg = blockIdx.y;

    #pragma unroll
    for (int i = 0; i < 12; i++) {
        int f = i*256 + tid;
        int q = f / 48, r = f % 48;
        *(float4*)&Es[q*196 + r*4] =
            *(const float4*)&g_e2pm[c*(64*576) + q*576 + pg*192 + r*4];
    }
    #pragma unroll
    for (int i = 0; i < 16; i++) {
        int f = i*256 + tid;
        int q = f >> 6, p = f & 63;
        int idx = (((p >> 3) - (q >> 3)) & 7)*8 + (((p & 7) - (q & 7)) & 7);
        Wp[f] = packpair(g_gg[c*64 + idx]);
    }
    __syncthreads();

    int pbase = (tid >> 5) * 8;
    ull acc[8][3];
    #pragma unroll
    for (int o = 0; o < 8; o++)
        #pragma unroll
        for (int g = 0; g < 3; g++) acc[o][g] = 0ull;

    #pragma unroll 8
    for (int q = 0; q < 64; q++) {
        ull A0 = *(const ull*)&Es[q*196 + 0*64 + 2*lane];
        ull A1 = *(const ull*)&Es[q*196 + 1*64 + 2*lane];
        ull A2 = *(const ull*)&Es[q*196 + 2*64 + 2*lane];
        const ulonglong2* wp = (const ulonglong2*)(Wp + q*64 + pbase);
        ulonglong2 w01 = wp[0], w23 = wp[1], w45 = wp[2], w67 = wp[3];
        ull wv[8] = {w01.x, w01.y, w23.x, w23.y, w45.x, w45.y, w67.x, w67.y};
        #pragma unroll
        for (int o = 0; o < 8; o++) {
            FMA2(acc[o][0], wv[o], A0, acc[o][0]);
            FMA2(acc[o][1], wv[o], A1, acc[o][1]);
            FMA2(acc[o][2], wv[o], A2, acc[o][2]);
        }
    }

    float* dst = g_fft + c*HWSZ;
    #pragma unroll
    for (int o = 0; o < 8; o++) {
        int p = pbase + o;
        int py = p >> 3, px = p & 7;
        #pragma unroll
        for (int g = 0; g < 3; g++) {
            int pat = pg*192 + g*64 + 2*lane;
            float lo = __uint_as_float((unsigned int)(acc[o][g] & 0xffffffffull));
            float hi = __uint_as_float((unsigned int)(acc[o][g] >> 32));
            dst[((pat/24)*8 + py)*WW + (pat%24)*8 + px] = lo;
            pat++;
            dst[((pat/24)*8 + py)*WW + (pat%24)*8 + px] = hi;
        }
    }
}

// ---------------- 3x3 conv (pad 1), input = g_fft + g_rev, 16x8 tile ----------------
#define C3_SMEM (33792 + 32768)

__global__ void __launch_bounds__(256, 2) k_conv3() {
    extern __shared__ char dsm[];
    float* Vsh = (float*)dsm;
    ull*   Wp  = (ull*)(dsm + 33792);

    int tid = threadIdx.x;
    int lane = tid & 31;
    int ot = (tid >> 5) * 8;
    int ph = blockIdx.y * 8, pw = blockIdx.x * 16;

    ull acc[8][2];
    #pragma unroll
    for (int o = 0; o < 8; o++)
        #pragma unroll
        for (int pr = 0; pr < 2; pr++) acc[o][pr] = 0ull;

    for (int k = 0; k < 9; k++) {
        int dy = k/3 - 1, dx = k%3 - 1;
        {
            const ulonglong2* wsrc = (const ulonglong2*)(g_wc2t2 + k*4096);
            ulonglong2* wdst = (ulonglong2*)Wp;
            #pragma unroll
            for (int i = 0; i < 8; i++) wdst[tid + i*256] = wsrc[tid + i*256];
        }
        #pragma unroll
        for (int i = 0; i < 32; i++) {
            int e = i*256 + tid;
            int c = e >> 7, p = e & 127;
            int h = ph + (p >> 4) + dy, w = pw + (p & 15) + dx;
            bool ok = (h >= 0) && (h < HH) && (w >= 0) && (w < WW);
            int sp = h*WW + w;
            Vsh[c*132 + p] = ok ? (g_fft[c*HWSZ + sp] + g_rev[c*HWSZ + sp]) : 0.f;
        }
        __syncthreads();

        #pragma unroll 8
        for (int c = 0; c < 64; c++) {
            union { float4 f; ull u[2]; } A;
            A.f = *(const float4*)&Vsh[c*132 + 4*lane];
            const ulonglong2* wp = (const ulonglong2*)(Wp + c*64 + ot);
            ulonglong2 w01 = wp[0], w23 = wp[1], w45 = wp[2], w67 = wp[3];
            ull wv[8] = {w01.x, w01.y, w23.x, w23.y, w45.x, w45.y, w67.x, w67.y};
            #pragma unroll
            for (int o = 0; o < 8; o++) {
                FMA2(acc[o][0], wv[o], A.u[0], acc[o][0]);
                FMA2(acc[o][1], wv[o], A.u[1], acc[o][1]);
            }
        }
        __syncthreads();
    }

    #pragma unroll
    for (int o = 0; o < 8; o++) {
        float* orow = g_e3 + (ot + o)*HWSZ;
        #pragma unroll
        for (int pr = 0; pr < 2; pr++) {
            int p0 = 4*lane + pr*2;
            int py = p0 >> 4, px = p0 & 15;
            *(ull*)(orow + (ph + py)*WW + pw + px) = acc[o][pr];
        }
    }
}

// ---------------- merged proj(128->128) + SimpleGate, 16x8 tile, 2/SM ----------------
#define PG_VA 0
#define PG_VB 33792
#define PG_W  67584
#define PG_SMEM 100352

__global__ void __launch_bounds__(256, 2) k_projgate(const float* __restrict__ dec,
                                                     float* __restrict__ out) {
    extern __shared__ char dsm[];
    float* Va = (float*)(dsm + PG_VA);
    float* Vb = (float*)(dsm + PG_VB);
    float* Wf = (float*)(dsm + PG_W);

    int tid = threadIdx.x;
    int lane = tid & 31;
    int ot = (tid >> 5) * 8;
    int ph = blockIdx.y * 8, pw = blockIdx.x * 16;

    #pragma unroll
    for (int i = 0; i < 32; i++) {
        int e = i*256 + tid;
        int c = e >> 7, p = e & 127;
        int sp = (ph + (p >> 4))*WW + pw + (p & 15);
        Va[c*132 + p] = g_e3[c*HWSZ + sp];
        Vb[c*132 + p] = dec[c*HWSZ + sp];
    }
    #pragma unroll
    for (int i = 0; i < 8; i++)
        ((float4*)Wf)[i*256 + tid] = ((const float4*)g_wpT)[i*256 + tid];
    __syncthreads();

    ull a1[8][2], a2[8][2];
    #pragma unroll
    for (int o = 0; o < 8; o++)
        #pragma unroll
        for (int pr = 0; pr < 2; pr++) { a1[o][pr] = 0ull; a2[o][pr] = 0ull; }

    #pragma unroll 4
    for (int c = 0; c < 64; c++) {
        union { float4 f; ull u[2]; } A;
        A.f = *(const float4*)&Va[c*132 + 4*lane];
        const float* wr = Wf + c*128;
        float4 wa = *(const float4*)(wr + ot);
        float4 wb = *(const float4*)(wr + ot + 4);
        float4 wc = *(const float4*)(wr + 64 + ot);
        float4 wd = *(const float4*)(wr + 64 + ot + 4);
        float w1v[8] = {wa.x, wa.y, wa.z, wa.w, wb.x, wb.y, wb.z, wb.w};
        float w2v[8] = {wc.x, wc.y, wc.z, wc.w, wd.x, wd.y, wd.z, wd.w};
        #pragma unroll
        for (int o = 0; o < 8; o++) {
            ull p1 = packpair(w1v[o]);
            ull p2 = packpair(w2v[o]);
            FMA2(a1[o][0], p1, A.u[0], a1[o][0]);
            FMA2(a1[o][1], p1, A.u[1], a1[o][1]);
            FMA2(a2[o][0], p2, A.u[0], a2[o][0]);
            FMA2(a2[o][1], p2, A.u[1], a2[o][1]);
        }
    }
    __syncthreads();
    #pragma unroll
    for (int i = 0; i < 8; i++)
        ((float4*)Wf)[i*256 + tid] = ((const float4*)(g_wpT + 64*128))[i*256 + tid];
    __syncthreads();

    #pragma unroll 4
    for (int c = 0; c < 64; c++) {
        union { float4 f; ull u[2]; } A;
        A.f = *(const float4*)&Vb[c*132 + 4*lane];
        const float* wr = Wf + c*128;
        float4 wa = *(const float4*)(wr + ot);
        float4 wb = *(const float4*)(wr + ot + 4);
        float4 wc = *(const float4*)(wr + 64 + ot);
        float4 wd = *(const float4*)(wr + 64 + ot + 4);
        float w1v[8] = {wa.x, wa.y, wa.z, wa.w, wb.x, wb.y, wb.z, wb.w};
        float w2v[8] = {wc.x, wc.y, wc.z, wc.w, wd.x, wd.y, wd.z, wd.w};
        #pragma unroll
        for (int o = 0; o < 8; o++) {
            ull p1 = packpair(w1v[o]);
            ull p2 = packpair(w2v[o]);
            FMA2(a1[o][0], p1, A.u[0], a1[o][0]);
            FMA2(a1[o][1], p1, A.u[1], a1[o][1]);
            FMA2(a2[o][0], p2, A.u[0], a2[o][0]);
            FMA2(a2[o][1], p2, A.u[1], a2[o][1]);
        }
    }

    #pragma unroll
    for (int o = 0; o < 8; o++) {
        float* orow = out + (ot + o)*HWSZ;
        #pragma unroll
        for (int pr = 0; pr < 2; pr++) {
            int p0 = 4*lane + pr*2;
            int py = p0 >> 4, px = p0 & 15;
            ull r;
            MUL2(r, a1[o][pr], a2[o][pr]);
            *(ull*)(orow + (ph + py)*WW + pw + px) = r;
        }
    }
}

extern "C" void kernel_launch(void* const* d_in, const int* in_sizes, int n_in,
                              void* d_out, int out_size) {
    const float* enc  = (const float*)d_in[0];
    const float* dec  = (const float*)d_in[1];
    const float* ioff = (const float*)d_in[2];
    const float* iw   = (const float*)d_in[3];
    const float* wpi  = (const float*)d_in[4];
    const float* fftw = (const float*)d_in[5];
    const float* wpo  = (const float*)d_in[6];
    const float* wdef = (const float*)d_in[7];
    const float* wc1  = (const float*)d_in[8];
    const float* wc2  = (const float*)d_in[9];
    float* out = (float*)d_out;

    cudaFuncSetAttribute(k_deform_wmma, cudaFuncAttributeMaxDynamicSharedMemorySize, DF_SMEM);
    cudaFuncSetAttribute(k_fftgemm,     cudaFuncAttributeMaxDynamicSharedMemorySize, FFT_SMEM);
    cudaFuncSetAttribute(k_conv3,       cudaFuncAttributeMaxDynamicSharedMemorySize, C3_SMEM);
    cudaFuncSetAttribute(k_projgate,    cudaFuncAttributeMaxDynamicSharedMemorySize, PG_SMEM);

    dim3 gdef(12, 24);    // 16w x 8h tiles
    dim3 gfft(64, 3);

    k_transpose  <<<576, 256>>>(enc);
    k_prep_wf    <<<(KTAPS*4096 + 255)/256, 256>>>(wc1, wdef);
    k_prep_g     <<<64, 64>>>(fftw);
    k_deform_wmma<<<gdef, 256, DF_SMEM>>>(ioff, iw);
    k_prep_tr    <<<144, 256>>>(wc2, wpo, wpi);
    k_conv1x1pm  <<<144, 128>>>(enc);
    k_fftgemm    <<<gfft, 256, FFT_SMEM>>>();
    k_conv3      <<<gdef, 256, C3_SMEM>>>();
    k_projgate   <<<gdef, 256, PG_SMEM>>>(dec, out);
}

// round 13
// speedup vs baseline: 1.5386x; 1.1631x over previous
#include <cuda_runtime.h>
#include <cuda_fp16.h>
#include <mma.h>
#include <cstdint>

using namespace nvcuda;

#define HH 192
#define WW 192
#define HWSZ (192*192)
#define CC 64
#define KTAPS 49
#define PADK 3

#define FMA2(d,a,b,c) asm("fma.rn.f32x2 %0, %1, %2, %3;" : "=l"(d) : "l"(a), "l"(b), "l"(c))

typedef unsigned long long ull;

__device__ __forceinline__ ull packpair(float v) {
    unsigned int u = __float_as_uint(v);
    return ((ull)u << 32) | u;
}
__device__ __forceinline__ ull pack2(float lo, float hi) {
    return ((ull)__float_as_uint(hi) << 32) | __float_as_uint(lo);
}

// ---------------- scratch (no allocs allowed) ----------------
__device__ float  g_rev [CC*HWSZ];
__device__ float  g_fft [CC*HWSZ];
__device__ __half g_encTh[HWSZ*CC];       // NHWC fp16
__device__ float  g_e2pm[CC*64*576];      // [c][q=64][patch=576]
__device__ __half g_wfh[KTAPS*64*64];     // [k][o][c] fp16 deform weight
__device__ __half g_wc3h[9*64*64];        // [k][o][c] fp16 conv3 hi
__device__ __half g_wc3l[9*64*64];        // [k][o][c] fp16 conv3 lo
__device__ __half g_wpf [128*128];        // [o128][j128] fp16 proj weight
__device__ ull    g_wpit2[64*64];         // [j][c] pairs
__device__ float  g_gg  [64*64];          // [c][a*8+d]

// ---------------- precompute: FFT filter -> circular conv kernel ----------------
__global__ void k_prep_g(const float* __restrict__ fw) {
    int c = blockIdx.x;
    int t = threadIdx.x;
    int a = t >> 3, d = t & 7;
    const float ct[8] = {1.f, 0.70710678118654752f, 0.f, -0.70710678118654752f,
                        -1.f, -0.70710678118654752f, 0.f, 0.70710678118654752f};
    const float st[8] = {0.f, 0.70710678118654752f, 1.f, 0.70710678118654752f,
                         0.f, -0.70710678118654752f, -1.f, -0.70710678118654752f};
    const float* w = fw + c * 40;
    float re = 0.f;
    for (int u = 0; u < 8; u++) {
        float rp = w[u*5+0] + ((d & 1) ? -w[u*5+4] : w[u*5+4]);
        float ip = 0.f;
        #pragma unroll
        for (int v = 1; v <= 3; v++) {
            int vd = (v * d) & 7;
            rp += 2.f * w[u*5+v] * ct[vd];
            ip += 2.f * w[u*5+v] * st[vd];
        }
        int ua = (u * a) & 7;
        re += ct[ua] * rp - st[ua] * ip;
    }
    g_gg[c*64 + t] = re * (1.f/64.f);
}

// ---------------- precompute: fused deform weight -> fp16 [k][o][c] ----------------
__global__ void k_prep_wf(const float* __restrict__ wc1, const float* __restrict__ wd) {
    int idx = blockIdx.x * blockDim.x + threadIdx.x;   // k*4096 + c*64 + o
    if (idx >= KTAPS*64*64) return;
    int o = idx & 63, c = (idx >> 6) & 63, k = idx >> 12;
    float s = 0.f;
    for (int m = 0; m < 64; m++)
        s += wc1[o*64 + m] * wd[(m*64 + c)*49 + k];
    g_wfh[k*4096 + o*64 + c] = __float2half(s);
}

// ---------------- precompute: conv3 fp16 hi/lo + proj fp16 + wpit pairs ----------------
__global__ void k_prep_tr(const float* __restrict__ wc2, const float* __restrict__ wpo,
                          const float* __restrict__ wpi) {
    int idx = blockIdx.x * blockDim.x + threadIdx.x;
    if (idx < 9*4096) {                          // [k][o][c] <- wc2[o][c][k]
        int o = idx & 63, c = (idx >> 6) & 63, k = idx >> 12;
        float s = wc2[(o*64 + c)*9 + k];
        __half hi = __float2half(s);
        float hv = __half2float(hi);
        g_wc3h[k*4096 + o*64 + c] = hi;
        g_wc3l[k*4096 + o*64 + c] = __float2half(s - hv);
    }
    if (idx < 128*128) {                         // [o][j] fp16 copy
        g_wpf[idx] = __float2half(wpo[idx]);
    }
    if (idx < 4096) {                            // [j][c] pairs
        int j = idx >> 6, c = idx & 63;
        g_wpit2[idx] = packpair(wpi[c*64 + j]);
    }
}

// ---------------- NCHW -> NHWC fp16 transpose of enc ----------------
__global__ void __launch_bounds__(256) k_transpose(const float* __restrict__ enc) {
    __shared__ float S[64][65];
    int tid = threadIdx.x;
    int p0 = blockIdx.x * 64;
    #pragma unroll
    for (int i = 0; i < 16; i++) {
        int e = i*256 + tid;
        S[e >> 6][e & 63] = enc[(e >> 6)*HWSZ + p0 + (e & 63)];
    }
    __syncthreads();
    #pragma unroll
    for (int i = 0; i < 8; i++) {
        int e2 = i*512 + tid*2;
        int lp = e2 >> 6, c = e2 & 63;
        __half2 hp = __floats2half2_rn(S[c][lp], S[c+1][lp]);
        *(__half2*)&g_encTh[p0*64 + e2] = hp;
    }
}

// ---------------- deform conv via WMMA fp16, 16x8 tile (unchanged from R10) ----------------
#define DF_VF   0
#define DF_WH   18432
#define DF_SIDX 27648
#define DF_SWT  29696
#define DF_SMEM 36864

__global__ void __launch_bounds__(256, 2) k_deform_wmma(const float* __restrict__ off,
                                                        const float* __restrict__ msk) {
    extern __shared__ char dsm[];
    __half* Vf = (__half*)(dsm + DF_VF);
    __half* Wh = (__half*)(dsm + DF_WH);
    int*   sIdx = (int*)(dsm + DF_SIDX);
    float* sWt  = (float*)(dsm + DF_SWT);
    const __half* encT = g_encTh;

    int tid = threadIdx.x;
    int wid = tid >> 5;
    int mg = wid & 3, ng = wid >> 2;
    int ph = blockIdx.y * 8, pw = blockIdx.x * 16;
    int ly = (tid & 127) >> 4, lx = tid & 15;
    int h = ph + ly, w = pw + lx;
    int sp = h * WW + w;

    wmma::fragment<wmma::accumulator, 16, 16, 16, float> dfr[2][2];
    #pragma unroll
    for (int mf = 0; mf < 2; mf++)
        #pragma unroll
        for (int nf = 0; nf < 2; nf++) wmma::fill_fragment(dfr[mf][nf], 0.f);

    for (int k = 0; k < KTAPS; k++) {
        #pragma unroll
        for (int i = 0; i < 2; i++) {
            int f = i*256 + tid;
            int row = f >> 3, ch = f & 7;
            *(float4*)((char*)Wh + row*144 + ch*16) =
                *(const float4*)(g_wfh + k*4096 + row*64 + ch*8);
        }
        if (tid < 128) {
            float dy = off[(2*k)*HWSZ + sp];
            float dx = off[(2*k+1)*HWSZ + sp];
            float m  = msk[k*HWSZ + sp];
            float yy = (float)(h - PADK + k/7) + dy;
            float xx = (float)(w - PADK + k%7) + dx;
            float y0f = floorf(yy), x0f = floorf(xx);
            float wy = yy - y0f, wx = xx - x0f;
            int y0 = (int)y0f, x0 = (int)x0f;
            int y1 = y0 + 1,   x1 = x0 + 1;
            bool vy0 = (y0 >= 0) && (y0 < HH), vy1 = (y1 >= 0) && (y1 < HH);
            bool vx0 = (x0 >= 0) && (x0 < WW), vx1 = (x1 >= 0) && (x1 < WW);
            int y0c = min(max(y0, 0), HH-1), y1c = min(max(y1, 0), HH-1);
            int x0c = min(max(x0, 0), WW-1), x1c = min(max(x1, 0), WW-1);
            sIdx[0*128 + tid] = (y0c*WW + x0c) * 64;
            sIdx[1*128 + tid] = (y0c*WW + x1c) * 64;
            sIdx[2*128 + tid] = (y1c*WW + x0c) * 64;
            sIdx[3*128 + tid] = (y1c*WW + x1c) * 64;
            sWt[0*128 + tid] = (vy0 && vx0) ? (1.f-wy)*(1.f-wx)*m : 0.f;
            sWt[1*128 + tid] = (vy0 && vx1) ? (1.f-wy)*wx*m       : 0.f;
            sWt[2*128 + tid] = (vy1 && vx0) ? wy*(1.f-wx)*m       : 0.f;
            sWt[3*128 + tid] = (vy1 && vx1) ? wy*wx*m             : 0.f;
        }
        __syncthreads();

        int c4 = tid & 15;
        #pragma unroll
        for (int it = 0; it < 2; it++) {
            int pq = (tid >> 4) + it * 16;
            int p0 = pq * 4;
            #pragma unroll
            for (int pp = 0; pp < 4; pp++) {
                int p = p0 + pp;
                uint2 q0 = *(const uint2*)(encT + sIdx[0*128 + p] + (c4 << 2));
                uint2 q1 = *(const uint2*)(encT + sIdx[1*128 + p] + (c4 << 2));
                uint2 q2 = *(const uint2*)(encT + sIdx[2*128 + p] + (c4 << 2));
                uint2 q3 = *(const uint2*)(encT + sIdx[3*128 + p] + (c4 << 2));
                float2 a0 = __half22float2(*(__half2*)&q0.x);
                float2 b0 = __half22float2(*(__half2*)&q0.y);
                float2 a1 = __half22float2(*(__half2*)&q1.x);
                float2 b1 = __half22float2(*(__half2*)&q1.y);
                float2 a2 = __half22float2(*(__half2*)&q2.x);
                float2 b2 = __half22float2(*(__half2*)&q2.y);
                float2 a3 = __half22float2(*(__half2*)&q3.x);
                float2 b3 = __half22float2(*(__half2*)&q3.y);
                float w0 = sWt[0*128 + p], w1 = sWt[1*128 + p];
                float w2 = sWt[2*128 + p], w3 = sWt[3*128 + p];
                float v0 = w0*a0.x + w1*a1.x + w2*a2.x + w3*a3.x;
                float v1 = w0*a0.y + w1*a1.y + w2*a2.y + w3*a3.y;
                float v2 = w0*b0.x + w1*b1.x + w2*b2.x + w3*b3.x;
                float v3 = w0*b0.y + w1*b1.y + w2*b2.y + w3*b3.y;
                uint32_t h01, h23;
                asm("cvt.rn.f16x2.f32 %0, %1, %2;" : "=r"(h01) : "f"(v1), "f"(v0));
                asm("cvt.rn.f16x2.f32 %0, %1, %2;" : "=r"(h23) : "f"(v3), "f"(v2));
                *(uint2*)((char*)Vf + p*144 + c4*8) = make_uint2(h01, h23);
            }
        }
        __syncthreads();

        #pragma unroll
        for (int kc = 0; kc < 4; kc++) {
            wmma::fragment<wmma::matrix_a, 16, 16, 16, __half, wmma::row_major> af[2];
            #pragma unroll
            for (int mf = 0; mf < 2; mf++)
                wmma::load_matrix_sync(af[mf], Vf + (mg*32 + mf*16)*72 + kc*16, 72);
            #pragma unroll
            for (int nf = 0; nf < 2; nf++) {
                wmma::fragment<wmma::matrix_b, 16, 16, 16, __half, wmma::col_major> bh;
                wmma::load_matrix_sync(bh, Wh + (ng*32 + nf*16)*72 + kc*16, 72);
                #pragma unroll
                for (int mf = 0; mf < 2; mf++)
                    wmma::mma_sync(dfr[mf][nf], af[mf], bh, dfr[mf][nf]);
            }
        }
        __syncthreads();
    }

    float* Dsh = (float*)dsm;
    #pragma unroll
    for (int mf = 0; mf < 2; mf++)
        #pragma unroll
        for (int nf = 0; nf < 2; nf++)
            wmma::store_matrix_sync(Dsh + (mg*32 + mf*16)*68 + ng*32 + nf*16,
                                    dfr[mf][nf], 68, wmma::mem_row_major);
    __syncthreads();
    {
        int p = tid & 127;
        int hf = tid >> 7;
        int base = (ph + (p >> 4))*WW + pw + (p & 15);
        #pragma unroll
        for (int i = 0; i < 32; i++) {
            int o = hf*32 + i;
            g_rev[o*HWSZ + base] = Dsh[p*68 + o];
        }
    }
}

// ---------------- 1x1 conv on enc -> patch-major e2pm, 128 thr, 256 px ----------------
__global__ void __launch_bounds__(128) k_conv1x1pm(const float* __restrict__ enc) {
    __shared__ ull Wt[64*64];
    int tid = threadIdx.x;
    {
        const ulonglong2* src = (const ulonglong2*)g_wpit2;
        ulonglong2* dst = (ulonglong2*)Wt;
        #pragma unroll
        for (int i = 0; i < 16; i++) dst[tid + i*128] = src[tid + i*128];
    }
    __syncthreads();

    int base = blockIdx.x * 256;
    int p = base + (tid & 7) + (tid >> 3) * 16;
    int p2 = p + 8;

    ull acc[64];
    #pragma unroll
    for (int c = 0; c < 64; c++) acc[c] = 0ull;

    for (int j = 0; j < 64; j++) {
        ull v = pack2(enc[j*HWSZ + p], enc[j*HWSZ + p2]);
        const ulonglong2* wrow = (const ulonglong2*)(Wt + j*64);
        #pragma unroll
        for (int cc = 0; cc < 32; cc++) {
            ulonglong2 wv = wrow[cc];
            FMA2(acc[2*cc],   wv.x, v, acc[2*cc]);
            FMA2(acc[2*cc+1], wv.y, v, acc[2*cc+1]);
        }
    }

    int h = p / 192, w = p % 192;
    int q = (h & 7)*8 + (w & 7);
    int pat = (h >> 3)*24 + (w >> 3);
    #pragma unroll
    for (int c = 0; c < 64; c++)
        *(ull*)&g_e2pm[c*(64*576) + q*576 + pat] = acc[c];
}

// ---------------- per-patch circular conv as dense GEMM per channel ----------------
#define FFT_SMEM (50176 + 32768)

__global__ void __launch_bounds__(256, 2) k_fftgemm() {
    extern __shared__ char dsm[];
    float* Es = (float*)dsm;
    ull*   Wp = (ull*)(dsm + 50176);

    int tid = threadIdx.x;
    int lane = tid & 31;
    int c = blockIdx.x, pg = blockIdx.y;

    #pragma unroll
    for (int i = 0; i < 12; i++) {
        int f = i*256 + tid;
        int q = f / 48, r = f % 48;
        *(float4*)&Es[q*196 + r*4] =
            *(const float4*)&g_e2pm[c*(64*576) + q*576 + pg*192 + r*4];
    }
    #pragma unroll
    for (int i = 0; i < 16; i++) {
        int f = i*256 + tid;
        int q = f >> 6, p = f & 63;
        int idx = (((p >> 3) - (q >> 3)) & 7)*8 + (((p & 7) - (q & 7)) & 7);
        Wp[f] = packpair(g_gg[c*64 + idx]);
    }
    __syncthreads();

    int pbase = (tid >> 5) * 8;
    ull acc[8][3];
    #pragma unroll
    for (int o = 0; o < 8; o++)
        #pragma unroll
        for (int g = 0; g < 3; g++) acc[o][g] = 0ull;

    #pragma unroll 8
    for (int q = 0; q < 64; q++) {
        ull A0 = *(const ull*)&Es[q*196 + 0*64 + 2*lane];
        ull A1 = *(const ull*)&Es[q*196 + 1*64 + 2*lane];
        ull A2 = *(const ull*)&Es[q*196 + 2*64 + 2*lane];
        const ulonglong2* wp = (const ulonglong2*)(Wp + q*64 + pbase);
        ulonglong2 w01 = wp[0], w23 = wp[1], w45 = wp[2], w67 = wp[3];
        ull wv[8] = {w01.x, w01.y, w23.x, w23.y, w45.x, w45.y, w67.x, w67.y};
        #pragma unroll
        for (int o = 0; o < 8; o++) {
            FMA2(acc[o][0], wv[o], A0, acc[o][0]);
            FMA2(acc[o][1], wv[o], A1, acc[o][1]);
            FMA2(acc[o][2], wv[o], A2, acc[o][2]);
        }
    }

    float* dst = g_fft + c*HWSZ;
    #pragma unroll
    for (int o = 0; o < 8; o++) {
        int p = pbase + o;
        int py = p >> 3, px = p & 7;
        #pragma unroll
        for (int g = 0; g < 3; g++) {
            int pat = pg*192 + g*64 + 2*lane;
            float lo = __uint_as_float((unsigned int)(acc[o][g] & 0xffffffffull));
            float hi = __uint_as_float((unsigned int)(acc[o][g] >> 32));
            dst[((pat/24)*8 + py)*WW + (pat%24)*8 + px] = lo;
            pat++;
            dst[((pat/24)*8 + py)*WW + (pat%24)*8 + px] = hi;
        }
    }
}

// ---------------- fused tail: conv3x3 (WMMA, W hi/lo) + proj(128->128) + gate ----------------
// smem regions (bytes):
//   A: 0..36864      Vf fp16[128][72] (conv3 staging) / Dsh float[128][68]
//   B: 36864..71680  E3f fp16[128][136] : e3 (cols 0:64) + dec (cols 64:128)
//   C: 71680..106496 conv3 Whi[64][72]+Wlo[64][72] then proj Wp fp16[128][136]
#define T_VF   0
#define T_E3   36864
#define T_W    71680
#define T_SMEM 106496

__global__ void __launch_bounds__(256, 2) k_tail(const float* __restrict__ dec,
                                                 float* __restrict__ out) {
    extern __shared__ char dsm[];
    __half* Vf  = (__half*)(dsm + T_VF);
    float*  Dsh = (float*)(dsm + T_VF);
    __half* E3f = (__half*)(dsm + T_E3);
    __half* Wa  = (__half*)(dsm + T_W);          // conv3 hi [64][72]
    __half* Wb  = (__half*)(dsm + T_W + 9216);   // conv3 lo [64][72]
    __half* Wp  = (__half*)(dsm + T_W);          // proj [128][136]

    int tid = threadIdx.x;
    int wid = tid >> 5;
    int mg = wid & 3, ng = wid >> 2;
    int ph = blockIdx.y * 8, pw = blockIdx.x * 16;

    wmma::fragment<wmma::accumulator, 16, 16, 16, float> a3[2][2];
    #pragma unroll
    for (int mf = 0; mf < 2; mf++)
        #pragma unroll
        for (int nf = 0; nf < 2; nf++) wmma::fill_fragment(a3[mf][nf], 0.f);

    // ---- conv3: 9 taps ----
    for (int k = 0; k < 9; k++) {
        int dy = k/3 - 1, dx = k%3 - 1;
        #pragma unroll
        for (int i = 0; i < 2; i++) {
            int f = i*256 + tid;
            int row = f >> 3, ch = f & 7;
            *(float4*)((char*)Wa + row*144 + ch*16) =
                *(const float4*)(g_wc3h + k*4096 + row*64 + ch*8);
            *(float4*)((char*)Wb + row*144 + ch*16) =
                *(const float4*)(g_wc3l + k*4096 + row*64 + ch*8);
        }
        #pragma unroll
        for (int i = 0; i < 32; i++) {
            int e = i*256 + tid;
            int c = e >> 7, p = e & 127;
            int h = ph + (p >> 4) + dy, w = pw + (p & 15) + dx;
            bool ok = (h >= 0) && (h < HH) && (w >= 0) && (w < WW);
            int sp = h*WW + w;
            float v = ok ? (g_fft[c*HWSZ + sp] + g_rev[c*HWSZ + sp]) : 0.f;
            Vf[p*72 + c] = __float2half(v);
        }
        __syncthreads();

        #pragma unroll
        for (int kc = 0; kc < 4; kc++) {
            wmma::fragment<wmma::matrix_a, 16, 16, 16, __half, wmma::row_major> af[2];
            #pragma unroll
            for (int mf = 0; mf < 2; mf++)
                wmma::load_matrix_sync(af[mf], Vf + (mg*32 + mf*16)*72 + kc*16, 72);
            #pragma unroll
            for (int nf = 0; nf < 2; nf++) {
                wmma::fragment<wmma::matrix_b, 16, 16, 16, __half, wmma::col_major> bh, bl;
                wmma::load_matrix_sync(bh, Wa + (ng*32 + nf*16)*72 + kc*16, 72);
                wmma::load_matrix_sync(bl, Wb + (ng*32 + nf*16)*72 + kc*16, 72);
                #pragma unroll
                for (int mf = 0; mf < 2; mf++) {
                    wmma::mma_sync(a3[mf][nf], af[mf], bh, a3[mf][nf]);
                    wmma::mma_sync(a3[mf][nf], af[mf], bl, a3[mf][nf]);
                }
            }
        }
        __syncthreads();
    }

    // ---- e3 frags -> Dsh (fp32) ----
    #pragma unroll
    for (int mf = 0; mf < 2; mf++)
        #pragma unroll
        for (int nf = 0; nf < 2; nf++)
            wmma::store_matrix_sync(Dsh + (mg*32 + mf*16)*68 + ng*32 + nf*16,
                                    a3[mf][nf], 68, wmma::mem_row_major);
    __syncthreads();

    // ---- build E3f = [e3 fp16 | dec fp16] ----
    {
        int p = tid & 127, hf = tid >> 7;
        int sp = (ph + (p >> 4))*WW + pw + (p & 15);
        #pragma unroll
        for (int i = 0; i < 32; i++) {
            int c = hf*32 + i;
            E3f[p*136 + c]      = __float2half(Dsh[p*68 + c]);
            E3f[p*136 + 64 + c] = __float2half(dec[c*HWSZ + sp]);
        }
    }
    __syncthreads();
    // ---- stage proj W: 128 rows x 128 halves = 2048 float4 chunks (FIXED: was 1024) ----
    #pragma unroll
    for (int i = 0; i < 8; i++) {
        int f = i*256 + tid;            // 0..2047 : row = f>>4 (128), ch = f&15
        int row = f >> 4, ch = f & 15;
        *(float4*)((char*)Wp + row*272 + ch*16) =
            *(const float4*)(g_wpf + row*128 + ch*8);
    }
    __syncthreads();

    // ---- proj: x1 = W[0:64]·[e3;dec], x2 = W[64:128]·[e3;dec] ----
    wmma::fragment<wmma::accumulator, 16, 16, 16, float> a1[2][2], a2[2][2];
    #pragma unroll
    for (int mf = 0; mf < 2; mf++)
        #pragma unroll
        for (int nf = 0; nf < 2; nf++) {
            wmma::fill_fragment(a1[mf][nf], 0.f);
            wmma::fill_fragment(a2[mf][nf], 0.f);
        }

    #pragma unroll
    for (int kc = 0; kc < 8; kc++) {
        wmma::fragment<wmma::matrix_a, 16, 16, 16, __half, wmma::row_major> af[2];
        #pragma unroll
        for (int mf = 0; mf < 2; mf++)
            wmma::load_matrix_sync(af[mf], E3f + (mg*32 + mf*16)*136 + kc*16, 136);
        #pragma unroll
        for (int nf = 0; nf < 2; nf++) {
            wmma::fragment<wmma::matrix_b, 16, 16, 16, __half, wmma::col_major> b1, b2;
            wmma::load_matrix_sync(b1, Wp + (ng*32 + nf*16)*136 + kc*16, 136);
            wmma::load_matrix_sync(b2, Wp + (64 + ng*32 + nf*16)*136 + kc*16, 136);
            #pragma unroll
            for (int mf = 0; mf < 2; mf++) {
                wmma::mma_sync(a1[mf][nf], af[mf], b1, a1[mf][nf]);
                wmma::mma_sync(a2[mf][nf], af[mf], b2, a2[mf][nf]);
            }
        }
    }

    // ---- gate elementwise on fragments (identical accumulator layouts) ----
    #pragma unroll
    for (int mf = 0; mf < 2; mf++)
        #pragma unroll
        for (int nf = 0; nf < 2; nf++)
            #pragma unroll
            for (int i = 0; i < a1[mf][nf].num_elements; i++)
                a1[mf][nf].x[i] *= a2[mf][nf].x[i];

    __syncthreads();
    #pragma unroll
    for (int mf = 0; mf < 2; mf++)
        #pragma unroll
        for (int nf = 0; nf < 2; nf++)
            wmma::store_matrix_sync(Dsh + (mg*32 + mf*16)*68 + ng*32 + nf*16,
                                    a1[mf][nf], 68, wmma::mem_row_major);
    __syncthreads();
    {
        int p = tid & 127, hf = tid >> 7;
        int base = (ph + (p >> 4))*WW + pw + (p & 15);
        #pragma unroll
        for (int i = 0; i < 32; i++) {
            int o = hf*32 + i;
            out[o*HWSZ + base] = Dsh[p*68 + o];
        }
    }
}

extern "C" void kernel_launch(void* const* d_in, const int* in_sizes, int n_in,
                              void* d_out, int out_size) {
    const float* enc  = (const float*)d_in[0];
    const float* dec  = (const float*)d_in[1];
    const float* ioff = (const float*)d_in[2];
    const float* iw   = (const float*)d_in[3];
    const float* wpi  = (const float*)d_in[4];
    const float* fftw = (const float*)d_in[5];
    const float* wpo  = (const float*)d_in[6];
    const float* wdef = (const float*)d_in[7];
    const float* wc1  = (const float*)d_in[8];
    const float* wc2  = (const float*)d_in[9];
    float* out = (float*)d_out;

    cudaFuncSetAttribute(k_deform_wmma, cudaFuncAttributeMaxDynamicSharedMemorySize, DF_SMEM);
    cudaFuncSetAttribute(k_fftgemm,     cudaFuncAttributeMaxDynamicSharedMemorySize, FFT_SMEM);
    cudaFuncSetAttribute(k_tail,        cudaFuncAttributeMaxDynamicSharedMemorySize, T_SMEM);

    dim3 gdef(12, 24);    // 16w x 8h tiles
    dim3 gfft(64, 3);

    k_transpose  <<<576, 256>>>(enc);
    k_prep_wf    <<<(KTAPS*4096 + 255)/256, 256>>>(wc1, wdef);
    k_prep_g     <<<64, 64>>>(fftw);
    k_deform_wmma<<<gdef, 256, DF_SMEM>>>(ioff, iw);
    k_prep_tr    <<<144, 256>>>(wc2, wpo, wpi);
    k_conv1x1pm  <<<144, 128>>>(enc);
    k_fftgemm    <<<gfft, 256, FFT_SMEM>>>();
    k_tail       <<<gdef, 256, T_SMEM>>>(dec, out);
}

// round 14
// speedup vs baseline: 1.8432x; 1.1980x over previous
#include <cuda_runtime.h>
#include <cuda_fp16.h>
#include <mma.h>
#include <cstdint>

using namespace nvcuda;

#define HH 192
#define WW 192
#define HWSZ (192*192)
#define CC 64
#define KTAPS 49
#define PADK 3

#define FMA2(d,a,b,c) asm("fma.rn.f32x2 %0, %1, %2, %3;" : "=l"(d) : "l"(a), "l"(b), "l"(c))

typedef unsigned long long ull;

__device__ __forceinline__ ull packpair(float v) {
    unsigned int u = __float_as_uint(v);
    return ((ull)u << 32) | u;
}
__device__ __forceinline__ ull pack2(float lo, float hi) {
    return ((ull)__float_as_uint(hi) << 32) | __float_as_uint(lo);
}

// ---------------- scratch (no allocs allowed) ----------------
__device__ float  g_rev [CC*HWSZ];
__device__ float  g_fft [CC*HWSZ];
__device__ __half g_encTh[HWSZ*CC];       // NHWC fp16
__device__ float  g_e2pm[CC*64*576];      // [c][q=64][patch=576]
__device__ __half g_wfh[KTAPS*64*64];     // [k][o][c] fp16 deform weight
__device__ __half g_wc3h[9*64*64];        // [k][o][c] fp16 conv3 hi
__device__ __half g_wc3l[9*64*64];        // [k][o][c] fp16 conv3 lo
__device__ __half g_wpf [128*128];        // [o128][j128] fp16 proj weight
__device__ ull    g_wpit2[64*64];         // [j][c] pairs
__device__ float  g_gg  [64*64];          // [c][a*8+d]

// ---------------- precompute: FFT filter -> circular conv kernel ----------------
__global__ void k_prep_g(const float* __restrict__ fw) {
    int c = blockIdx.x;
    int t = threadIdx.x;
    int a = t >> 3, d = t & 7;
    const float ct[8] = {1.f, 0.70710678118654752f, 0.f, -0.70710678118654752f,
                        -1.f, -0.70710678118654752f, 0.f, 0.70710678118654752f};
    const float st[8] = {0.f, 0.70710678118654752f, 1.f, 0.70710678118654752f,
                         0.f, -0.70710678118654752f, -1.f, -0.70710678118654752f};
    const float* w = fw + c * 40;
    float re = 0.f;
    for (int u = 0; u < 8; u++) {
        float rp = w[u*5+0] + ((d & 1) ? -w[u*5+4] : w[u*5+4]);
        float ip = 0.f;
        #pragma unroll
        for (int v = 1; v <= 3; v++) {
            int vd = (v * d) & 7;
            rp += 2.f * w[u*5+v] * ct[vd];
            ip += 2.f * w[u*5+v] * st[vd];
        }
        int ua = (u * a) & 7;
        re += ct[ua] * rp - st[ua] * ip;
    }
    g_gg[c*64 + t] = re * (1.f/64.f);
}

// ---------------- precompute: fused deform weight -> fp16 [k][o][c] ----------------
__global__ void k_prep_wf(const float* __restrict__ wc1, const float* __restrict__ wd) {
    int idx = blockIdx.x * blockDim.x + threadIdx.x;   // k*4096 + c*64 + o
    if (idx >= KTAPS*64*64) return;
    int o = idx & 63, c = (idx >> 6) & 63, k = idx >> 12;
    float s = 0.f;
    for (int m = 0; m < 64; m++)
        s += wc1[o*64 + m] * wd[(m*64 + c)*49 + k];
    g_wfh[k*4096 + o*64 + c] = __float2half(s);
}

// ---------------- precompute: conv3 fp16 hi/lo + proj fp16 + wpit pairs ----------------
__global__ void k_prep_tr(const float* __restrict__ wc2, const float* __restrict__ wpo,
                          const float* __restrict__ wpi) {
    int idx = blockIdx.x * blockDim.x + threadIdx.x;
    if (idx < 9*4096) {                          // [k][o][c] <- wc2[o][c][k]
        int o = idx & 63, c = (idx >> 6) & 63, k = idx >> 12;
        float s = wc2[(o*64 + c)*9 + k];
        __half hi = __float2half(s);
        float hv = __half2float(hi);
        g_wc3h[k*4096 + o*64 + c] = hi;
        g_wc3l[k*4096 + o*64 + c] = __float2half(s - hv);
    }
    if (idx < 128*128) {                         // [o][j] fp16 copy
        g_wpf[idx] = __float2half(wpo[idx]);
    }
    if (idx < 4096) {                            // [j][c] pairs
        int j = idx >> 6, c = idx & 63;
        g_wpit2[idx] = packpair(wpi[c*64 + j]);
    }
}

// ---------------- NCHW -> NHWC fp16 transpose of enc ----------------
__global__ void __launch_bounds__(256) k_transpose(const float* __restrict__ enc) {
    __shared__ float S[64][65];
    int tid = threadIdx.x;
    int p0 = blockIdx.x * 64;
    #pragma unroll
    for (int i = 0; i < 16; i++) {
        int e = i*256 + tid;
        S[e >> 6][e & 63] = enc[(e >> 6)*HWSZ + p0 + (e & 63)];
    }
    __syncthreads();
    #pragma unroll
    for (int i = 0; i < 8; i++) {
        int e2 = i*512 + tid*2;
        int lp = e2 >> 6, c = e2 & 63;
        __half2 hp = __floats2half2_rn(S[c][lp], S[c+1][lp]);
        *(__half2*)&g_encTh[p0*64 + e2] = hp;
    }
}

// ---------------- deform conv via WMMA fp16, 16x8 tile, uint4 gather ----------------
#define DF_VF   0
#define DF_WH   18432
#define DF_SIDX 27648
#define DF_SWT  29696
#define DF_SMEM 36864

__global__ void __launch_bounds__(256, 2) k_deform_wmma(const float* __restrict__ off,
                                                        const float* __restrict__ msk) {
    extern __shared__ char dsm[];
    __half* Vf = (__half*)(dsm + DF_VF);
    __half* Wh = (__half*)(dsm + DF_WH);
    int*   sIdx = (int*)(dsm + DF_SIDX);
    float* sWt  = (float*)(dsm + DF_SWT);
    const __half* encT = g_encTh;

    int tid = threadIdx.x;
    int wid = tid >> 5;
    int mg = wid & 3, ng = wid >> 2;
    int ph = blockIdx.y * 8, pw = blockIdx.x * 16;
    int ly = (tid & 127) >> 4, lx = tid & 15;
    int h = ph + ly, w = pw + lx;
    int sp = h * WW + w;

    wmma::fragment<wmma::accumulator, 16, 16, 16, float> dfr[2][2];
    #pragma unroll
    for (int mf = 0; mf < 2; mf++)
        #pragma unroll
        for (int nf = 0; nf < 2; nf++) wmma::fill_fragment(dfr[mf][nf], 0.f);

    for (int k = 0; k < KTAPS; k++) {
        #pragma unroll
        for (int i = 0; i < 2; i++) {
            int f = i*256 + tid;
            int row = f >> 3, ch = f & 7;
            *(float4*)((char*)Wh + row*144 + ch*16) =
                *(const float4*)(g_wfh + k*4096 + row*64 + ch*8);
        }
        if (tid < 128) {
            float dy = off[(2*k)*HWSZ + sp];
            float dx = off[(2*k+1)*HWSZ + sp];
            float m  = msk[k*HWSZ + sp];
            float yy = (float)(h - PADK + k/7) + dy;
            float xx = (float)(w - PADK + k%7) + dx;
            float y0f = floorf(yy), x0f = floorf(xx);
            float wy = yy - y0f, wx = xx - x0f;
            int y0 = (int)y0f, x0 = (int)x0f;
            int y1 = y0 + 1,   x1 = x0 + 1;
            bool vy0 = (y0 >= 0) && (y0 < HH), vy1 = (y1 >= 0) && (y1 < HH);
            bool vx0 = (x0 >= 0) && (x0 < WW), vx1 = (x1 >= 0) && (x1 < WW);
            int y0c = min(max(y0, 0), HH-1), y1c = min(max(y1, 0), HH-1);
            int x0c = min(max(x0, 0), WW-1), x1c = min(max(x1, 0), WW-1);
            sIdx[0*128 + tid] = (y0c*WW + x0c) * 64;
            sIdx[1*128 + tid] = (y0c*WW + x1c) * 64;
            sIdx[2*128 + tid] = (y1c*WW + x0c) * 64;
            sIdx[3*128 + tid] = (y1c*WW + x1c) * 64;
            sWt[0*128 + tid] = (vy0 && vx0) ? (1.f-wy)*(1.f-wx)*m : 0.f;
            sWt[1*128 + tid] = (vy0 && vx1) ? (1.f-wy)*wx*m       : 0.f;
            sWt[2*128 + tid] = (vy1 && vx0) ? wy*(1.f-wx)*m       : 0.f;
            sWt[3*128 + tid] = (vy1 && vx1) ? wy*wx*m             : 0.f;
        }
        __syncthreads();

        // ---- gather: uint4 (8 channels/thread), bilinear fp32 -> fp16 ----
        int c8 = tid & 7;
        #pragma unroll
        for (int it = 0; it < 4; it++) {
            int p = (tid >> 3) + it * 32;
            uint4 q0 = *(const uint4*)(encT + sIdx[0*128 + p] + (c8 << 3));
            uint4 q1 = *(const uint4*)(encT + sIdx[1*128 + p] + (c8 << 3));
            uint4 q2 = *(const uint4*)(encT + sIdx[2*128 + p] + (c8 << 3));
            uint4 q3 = *(const uint4*)(encT + sIdx[3*128 + p] + (c8 << 3));
            float w0 = sWt[0*128 + p], w1 = sWt[1*128 + p];
            float w2 = sWt[2*128 + p], w3 = sWt[3*128 + p];
            const uint32_t* u0 = (const uint32_t*)&q0;
            const uint32_t* u1 = (const uint32_t*)&q1;
            const uint32_t* u2 = (const uint32_t*)&q2;
            const uint32_t* u3 = (const uint32_t*)&q3;
            uint32_t r[4];
            #pragma unroll
            for (int j = 0; j < 4; j++) {
                float2 a0 = __half22float2(*(const __half2*)&u0[j]);
                float2 a1 = __half22float2(*(const __half2*)&u1[j]);
                float2 a2 = __half22float2(*(const __half2*)&u2[j]);
                float2 a3 = __half22float2(*(const __half2*)&u3[j]);
                float vx = w0*a0.x + w1*a1.x + w2*a2.x + w3*a3.x;
                float vy = w0*a0.y + w1*a1.y + w2*a2.y + w3*a3.y;
                asm("cvt.rn.f16x2.f32 %0, %1, %2;" : "=r"(r[j]) : "f"(vy), "f"(vx));
            }
            *(uint4*)((char*)Vf + p*144 + (c8 << 4)) = *(uint4*)r;
        }
        __syncthreads();

        #pragma unroll
        for (int kc = 0; kc < 4; kc++) {
            wmma::fragment<wmma::matrix_a, 16, 16, 16, __half, wmma::row_major> af[2];
            #pragma unroll
            for (int mf = 0; mf < 2; mf++)
                wmma::load_matrix_sync(af[mf], Vf + (mg*32 + mf*16)*72 + kc*16, 72);
            #pragma unroll
            for (int nf = 0; nf < 2; nf++) {
                wmma::fragment<wmma::matrix_b, 16, 16, 16, __half, wmma::col_major> bh;
                wmma::load_matrix_sync(bh, Wh + (ng*32 + nf*16)*72 + kc*16, 72);
                #pragma unroll
                for (int mf = 0; mf < 2; mf++)
                    wmma::mma_sync(dfr[mf][nf], af[mf], bh, dfr[mf][nf]);
            }
        }
        __syncthreads();
    }

    float* Dsh = (float*)dsm;
    #pragma unroll
    for (int mf = 0; mf < 2; mf++)
        #pragma unroll
        for (int nf = 0; nf < 2; nf++)
            wmma::store_matrix_sync(Dsh + (mg*32 + mf*16)*68 + ng*32 + nf*16,
                                    dfr[mf][nf], 68, wmma::mem_row_major);
    __syncthreads();
    {
        int p = tid & 127;
        int hf = tid >> 7;
        int base = (ph + (p >> 4))*WW + pw + (p & 15);
        #pragma unroll
        for (int i = 0; i < 32; i++) {
            int o = hf*32 + i;
            g_rev[o*HWSZ + base] = Dsh[p*68 + o];
        }
    }
}

// ---------------- 1x1 conv on enc -> patch-major e2pm, 128 thr, 256 px ----------------
__global__ void __launch_bounds__(128) k_conv1x1pm(const float* __restrict__ enc) {
    __shared__ ull Wt[64*64];
    int tid = threadIdx.x;
    {
        const ulonglong2* src = (const ulonglong2*)g_wpit2;
        ulonglong2* dst = (ulonglong2*)Wt;
        #pragma unroll
        for (int i = 0; i < 16; i++) dst[tid + i*128] = src[tid + i*128];
    }
    __syncthreads();

    int base = blockIdx.x * 256;
    int p = base + (tid & 7) + (tid >> 3) * 16;
    int p2 = p + 8;

    ull acc[64];
    #pragma unroll
    for (int c = 0; c < 64; c++) acc[c] = 0ull;

    for (int j = 0; j < 64; j++) {
        ull v = pack2(enc[j*HWSZ + p], enc[j*HWSZ + p2]);
        const ulonglong2* wrow = (const ulonglong2*)(Wt + j*64);
        #pragma unroll
        for (int cc = 0; cc < 32; cc++) {
            ulonglong2 wv = wrow[cc];
            FMA2(acc[2*cc],   wv.x, v, acc[2*cc]);
            FMA2(acc[2*cc+1], wv.y, v, acc[2*cc+1]);
        }
    }

    int h = p / 192, w = p % 192;
    int q = (h & 7)*8 + (w & 7);
    int pat = (h >> 3)*24 + (w >> 3);
    #pragma unroll
    for (int c = 0; c < 64; c++)
        *(ull*)&g_e2pm[c*(64*576) + q*576 + pat] = acc[c];
}

// ---------------- per-patch circular conv as dense GEMM per channel ----------------
#define FFT_SMEM (50176 + 32768)

__global__ void __launch_bounds__(256, 2) k_fftgemm() {
    extern __shared__ char dsm[];
    float* Es = (float*)dsm;
    ull*   Wp = (ull*)(dsm + 50176);

    int tid = threadIdx.x;
    int lane = tid & 31;
    int c = blockIdx.x, pg = blockIdx.y;

    #pragma unroll
    for (int i = 0; i < 12; i++) {
        int f = i*256 + tid;
        int q = f / 48, r = f % 48;
        *(float4*)&Es[q*196 + r*4] =
            *(const float4*)&g_e2pm[c*(64*576) + q*576 + pg*192 + r*4];
    }
    #pragma unroll
    for (int i = 0; i < 16; i++) {
        int f = i*256 + tid;
        int q = f >> 6, p = f & 63;
        int idx = (((p >> 3) - (q >> 3)) & 7)*8 + (((p & 7) - (q & 7)) & 7);
        Wp[f] = packpair(g_gg[c*64 + idx]);
    }
    __syncthreads();

    int pbase = (tid >> 5) * 8;
    ull acc[8][3];
    #pragma unroll
    for (int o = 0; o < 8; o++)
        #pragma unroll
        for (int g = 0; g < 3; g++) acc[o][g] = 0ull;

    #pragma unroll 8
    for (int q = 0; q < 64; q++) {
        ull A0 = *(const ull*)&Es[q*196 + 0*64 + 2*lane];
        ull A1 = *(const ull*)&Es[q*196 + 1*64 + 2*lane];
        ull A2 = *(const ull*)&Es[q*196 + 2*64 + 2*lane];
        const ulonglong2* wp = (const ulonglong2*)(Wp + q*64 + pbase);
        ulonglong2 w01 = wp[0], w23 = wp[1], w45 = wp[2], w67 = wp[3];
        ull wv[8] = {w01.x, w01.y, w23.x, w23.y, w45.x, w45.y, w67.x, w67.y};
        #pragma unroll
        for (int o = 0; o < 8; o++) {
            FMA2(acc[o][0], wv[o], A0, acc[o][0]);
            FMA2(acc[o][1], wv[o], A1, acc[o][1]);
            FMA2(acc[o][2], wv[o], A2, acc[o][2]);
        }
    }

    float* dst = g_fft + c*HWSZ;
    #pragma unroll
    for (int o = 0; o < 8; o++) {
        int p = pbase + o;
        int py = p >> 3, px = p & 7;
        #pragma unroll
        for (int g = 0; g < 3; g++) {
            int pat = pg*192 + g*64 + 2*lane;
            float lo = __uint_as_float((unsigned int)(acc[o][g] & 0xffffffffull));
            float hi = __uint_as_float((unsigned int)(acc[o][g] >> 32));
            dst[((pat/24)*8 + py)*WW + (pat%24)*8 + px] = lo;
            pat++;
            dst[((pat/24)*8 + py)*WW + (pat%24)*8 + px] = hi;
        }
    }
}

// ---------------- fused tail: halo + conv3x3 (WMMA, W hi/lo) + proj + gate ----------------
// smem regions (bytes):
//   HS  : 0..23040        halo fp16[64][180] (10h x 18w, zero-padded borders)
//   WC3 : 23040..41472    conv3 Whi[64][72] + Wlo[64][72]
//   VF  : 41472..76288    Vf fp16[128][72] (taps) / Dsh float[128][68] (after)
//   E3F : 76288..111104   E3f fp16[128][136] : e3 | dec
//   WPJ : overlays 0..34816 (halo+part WC3) after conv3 completes
#define T_HS   0
#define T_WC3  23040
#define T_VF   41472
#define T_E3   76288
#define T_SMEM 111104

__global__ void __launch_bounds__(256, 2) k_tail(const float* __restrict__ dec,
                                                 float* __restrict__ out) {
    extern __shared__ char dsm[];
    __half* HS  = (__half*)(dsm + T_HS);
    __half* Wa  = (__half*)(dsm + T_WC3);
    __half* Wb  = (__half*)(dsm + T_WC3 + 9216);
    __half* Vf  = (__half*)(dsm + T_VF);
    float*  Dsh = (float*)(dsm + T_VF);
    __half* E3f = (__half*)(dsm + T_E3);
    __half* Wp  = (__half*)(dsm + T_HS);         // overlay after conv3

    int tid = threadIdx.x;
    int wid = tid >> 5;
    int mg = wid & 3, ng = wid >> 2;
    int ph = blockIdx.y * 8, pw = blockIdx.x * 16;

    // ---- halo load: fp16(g_fft + g_rev), zero-padded ----
    for (int i = tid; i < 64*180; i += 256) {
        int c = i / 180, t = i - c*180;
        int hy = ph - 1 + t / 18, wx = pw - 1 + (t % 18);
        bool ok = (hy >= 0) && (hy < HH) && (wx >= 0) && (wx < WW);
        int sp = hy*WW + wx;
        float v = ok ? (g_fft[c*HWSZ + sp] + g_rev[c*HWSZ + sp]) : 0.f;
        HS[i] = __float2half(v);
    }

    wmma::fragment<wmma::accumulator, 16, 16, 16, float> a3[2][2];
    #pragma unroll
    for (int mf = 0; mf < 2; mf++)
        #pragma unroll
        for (int nf = 0; nf < 2; nf++) wmma::fill_fragment(a3[mf][nf], 0.f);

    // ---- conv3: 9 taps, staging from smem halo ----
    for (int k = 0; k < 9; k++) {
        int dy = k/3 - 1, dx = k%3 - 1;
        #pragma unroll
        for (int i = 0; i < 2; i++) {
            int f = i*256 + tid;
            int row = f >> 3, ch = f & 7;
            *(float4*)((char*)Wa + row*144 + ch*16) =
                *(const float4*)(g_wc3h + k*4096 + row*64 + ch*8);
            *(float4*)((char*)Wb + row*144 + ch*16) =
                *(const float4*)(g_wc3l + k*4096 + row*64 + ch*8);
        }
        __syncthreads();
        #pragma unroll
        for (int i = 0; i < 32; i++) {
            int e = i*256 + tid;
            int c = e >> 7, p = e & 127;
            Vf[p*72 + c] = HS[c*180 + ((p >> 4) + 1 + dy)*18 + (p & 15) + 1 + dx];
        }
        __syncthreads();

        #pragma unroll
        for (int kc = 0; kc < 4; kc++) {
            wmma::fragment<wmma::matrix_a, 16, 16, 16, __half, wmma::row_major> af[2];
            #pragma unroll
            for (int mf = 0; mf < 2; mf++)
                wmma::load_matrix_sync(af[mf], Vf + (mg*32 + mf*16)*72 + kc*16, 72);
            #pragma unroll
            for (int nf = 0; nf < 2; nf++) {
                wmma::fragment<wmma::matrix_b, 16, 16, 16, __half, wmma::col_major> bh, bl;
                wmma::load_matrix_sync(bh, Wa + (ng*32 + nf*16)*72 + kc*16, 72);
                wmma::load_matrix_sync(bl, Wb + (ng*32 + nf*16)*72 + kc*16, 72);
                #pragma unroll
                for (int mf = 0; mf < 2; mf++) {
                    wmma::mma_sync(a3[mf][nf], af[mf], bh, a3[mf][nf]);
                    wmma::mma_sync(a3[mf][nf], af[mf], bl, a3[mf][nf]);
                }
            }
        }
        __syncthreads();
    }

    // ---- e3 frags -> Dsh (fp32) ----
    #pragma unroll
    for (int mf = 0; mf < 2; mf++)
        #pragma unroll
        for (int nf = 0; nf < 2; nf++)
            wmma::store_matrix_sync(Dsh + (mg*32 + mf*16)*68 + ng*32 + nf*16,
                                    a3[mf][nf], 68, wmma::mem_row_major);
    __syncthreads();

    // ---- build E3f = [e3 fp16 | dec fp16] ----
    {
        int p = tid & 127, hf = tid >> 7;
        int sp = (ph + (p >> 4))*WW + pw + (p & 15);
        #pragma unroll
        for (int i = 0; i < 32; i++) {
            int c = hf*32 + i;
            E3f[p*136 + c]      = __float2half(Dsh[p*68 + c]);
            E3f[p*136 + 64 + c] = __float2half(dec[c*HWSZ + sp]);
        }
    }
    __syncthreads();
    // ---- stage proj W (overlays halo region): 128 rows x 128 halves ----
    #pragma unroll
    for (int i = 0; i < 8; i++) {
        int f = i*256 + tid;            // 0..2047 : row = f>>4 (128), ch = f&15
        int row = f >> 4, ch = f & 15;
        *(float4*)((char*)Wp + row*272 + ch*16) =
            *(const float4*)(g_wpf + row*128 + ch*8);
    }
    __syncthreads();

    // ---- proj: x1 = W[0:64]·[e3;dec], x2 = W[64:128]·[e3;dec] ----
    wmma::fragment<wmma::accumulator, 16, 16, 16, float> a1[2][2], a2[2][2];
    #pragma unroll
    for (int mf = 0; mf < 2; mf++)
        #pragma unroll
        for (int nf = 0; nf < 2; nf++) {
            wmma::fill_fragment(a1[mf][nf], 0.f);
            wmma::fill_fragment(a2[mf][nf], 0.f);
        }

    #pragma unroll
    for (int kc = 0; kc < 8; kc++) {
        wmma::fragment<wmma::matrix_a, 16, 16, 16, __half, wmma::row_major> af[2];
        #pragma unroll
        for (int mf = 0; mf < 2; mf++)
            wmma::load_matrix_sync(af[mf], E3f + (mg*32 + mf*16)*136 + kc*16, 136);
        #pragma unroll
        for (int nf = 0; nf < 2; nf++) {
            wmma::fragment<wmma::matrix_b, 16, 16, 16, __half, wmma::col_major> b1, b2;
            wmma::load_matrix_sync(b1, Wp + (ng*32 + nf*16)*136 + kc*16, 136);
            wmma::load_matrix_sync(b2, Wp + (64 + ng*32 + nf*16)*136 + kc*16, 136);
            #pragma unroll
            for (int mf = 0; mf < 2; mf++) {
                wmma::mma_sync(a1[mf][nf], af[mf], b1, a1[mf][nf]);
                wmma::mma_sync(a2[mf][nf], af[mf], b2, a2[mf][nf]);
            }
        }
    }

    // ---- gate elementwise on fragments ----
    #pragma unroll
    for (int mf = 0; mf < 2; mf++)
        #pragma unroll
        for (int nf = 0; nf < 2; nf++)
            #pragma unroll
            for (int i = 0; i < a1[mf][nf].num_elements; i++)
                a1[mf][nf].x[i] *= a2[mf][nf].x[i];

    __syncthreads();
    #pragma unroll
    for (int mf = 0; mf < 2; mf++)
        #pragma unroll
        for (int nf = 0; nf < 2; nf++)
            wmma::store_matrix_sync(Dsh + (mg*32 + mf*16)*68 + ng*32 + nf*16,
                                    a1[mf][nf], 68, wmma::mem_row_major);
    __syncthreads();
    {
        int p = tid & 127, hf = tid >> 7;
        int base = (ph + (p >> 4))*WW + pw + (p & 15);
        #pragma unroll
        for (int i = 0; i < 32; i++) {
            int o = hf*32 + i;
            out[o*HWSZ + base] = Dsh[p*68 + o];
        }
    }
}

extern "C" void kernel_launch(void* const* d_in, const int* in_sizes, int n_in,
                              void* d_out, int out_size) {
    const float* enc  = (const float*)d_in[0];
    const float* dec  = (const float*)d_in[1];
    const float* ioff = (const float*)d_in[2];
    const float* iw   = (const float*)d_in[3];
    const float* wpi  = (const float*)d_in[4];
    const float* fftw = (const float*)d_in[5];
    const float* wpo  = (const float*)d_in[6];
    const float* wdef = (const float*)d_in[7];
    const float* wc1  = (const float*)d_in[8];
    const float* wc2  = (const float*)d_in[9];
    float* out = (float*)d_out;

    cudaFuncSetAttribute(k_deform_wmma, cudaFuncAttributeMaxDynamicSharedMemorySize, DF_SMEM);
    cudaFuncSetAttribute(k_fftgemm,     cudaFuncAttributeMaxDynamicSharedMemorySize, FFT_SMEM);
    cudaFuncSetAttribute(k_tail,        cudaFuncAttributeMaxDynamicSharedMemorySize, T_SMEM);

    dim3 gdef(12, 24);    // 16w x 8h tiles
    dim3 gfft(64, 3);

    k_transpose  <<<576, 256>>>(enc);
    k_prep_wf    <<<(KTAPS*4096 + 255)/256, 256>>>(wc1, wdef);
    k_prep_g     <<<64, 64>>>(fftw);
    k_deform_wmma<<<gdef, 256, DF_SMEM>>>(ioff, iw);
    k_prep_tr    <<<144, 256>>>(wc2, wpo, wpi);
    k_conv1x1pm  <<<144, 128>>>(enc);
    k_fftgemm    <<<gfft, 256, FFT_SMEM>>>();
    k_tail       <<<gdef, 256, T_SMEM>>>(dec, out);
}